// round 1
// baseline (speedup 1.0000x reference)
#include <cuda_runtime.h>
#include <cstdint>

// Problem constants
#define B_SZ    2
#define T_SEQ   2048
#define D_MODEL 1024
#define H_HEADS 16
#define DK      64
#define M_ROWS  (B_SZ * T_SEQ)   // 4096
#define WIN     64
#define MAXD    128

// ---------------------------------------------------------------------------
// Scratch (device globals: allocation-free per harness rules)
// ---------------------------------------------------------------------------
__device__ float g_Q[(size_t)M_ROWS * D_MODEL];
__device__ float g_K[(size_t)M_ROWS * D_MODEL];
__device__ float g_V[(size_t)M_ROWS * D_MODEL];
__device__ float g_A[(size_t)M_ROWS * D_MODEL];

// ---------------------------------------------------------------------------
// SGEMM: C[M x N] = A[M x K] @ B[K x N] + bias[N]
// 128x128 block tile, BK=8, 256 threads, 8x8 microtile (2x2 quadrants),
// double-buffered shared memory.
// ---------------------------------------------------------------------------
#define BM 128
#define BN 128
#define BK 8

__global__ __launch_bounds__(256, 2) void sgemm_bias(
    const float* __restrict__ A, const float* __restrict__ B,
    const float* __restrict__ bias, float* __restrict__ C)
{
    const int N = D_MODEL, K = D_MODEL;
    __shared__ float As[2][BK][BM];
    __shared__ float Bs[2][BK][BN];

    const int tid = threadIdx.x;
    const int bm  = blockIdx.y * BM;
    const int bn  = blockIdx.x * BN;

    // A-tile loader: 128 rows x 8 cols, float4 per thread
    const int a_row = tid >> 1;
    const int a_col = (tid & 1) * 4;
    // B-tile loader: 8 rows x 128 cols, float4 per thread
    const int b_row = tid >> 5;
    const int b_col = (tid & 31) * 4;
    // Compute mapping: 16x16 thread grid, 2x2 quadrants of 4x4
    const int tx = tid & 15;
    const int ty = tid >> 4;

    float acc[8][8];
#pragma unroll
    for (int i = 0; i < 8; i++)
#pragma unroll
        for (int j = 0; j < 8; j++) acc[i][j] = 0.f;

    // Preload panel 0
    {
        float4 av = *(const float4*)(A + (size_t)(bm + a_row) * K + a_col);
        As[0][a_col + 0][a_row] = av.x;
        As[0][a_col + 1][a_row] = av.y;
        As[0][a_col + 2][a_row] = av.z;
        As[0][a_col + 3][a_row] = av.w;
        float4 bv = *(const float4*)(B + (size_t)b_row * N + bn + b_col);
        *(float4*)&Bs[0][b_row][b_col] = bv;
    }
    __syncthreads();

    int buf = 0;
    for (int kp = 0; kp < K; kp += BK) {
        float4 apre, bpre;
        const bool has_next = (kp + BK) < K;
        if (has_next) {
            apre = *(const float4*)(A + (size_t)(bm + a_row) * K + (kp + BK) + a_col);
            bpre = *(const float4*)(B + (size_t)(kp + BK + b_row) * N + bn + b_col);
        }

#pragma unroll
        for (int kk = 0; kk < BK; kk++) {
            float a[8], b[8];
            *(float4*)&a[0] = *(const float4*)&As[buf][kk][ty * 4];
            *(float4*)&a[4] = *(const float4*)&As[buf][kk][64 + ty * 4];
            *(float4*)&b[0] = *(const float4*)&Bs[buf][kk][tx * 4];
            *(float4*)&b[4] = *(const float4*)&Bs[buf][kk][64 + tx * 4];
#pragma unroll
            for (int i = 0; i < 8; i++)
#pragma unroll
                for (int j = 0; j < 8; j++)
                    acc[i][j] += a[i] * b[j];
        }

        if (has_next) {
            As[buf ^ 1][a_col + 0][a_row] = apre.x;
            As[buf ^ 1][a_col + 1][a_row] = apre.y;
            As[buf ^ 1][a_col + 2][a_row] = apre.z;
            As[buf ^ 1][a_col + 3][a_row] = apre.w;
            *(float4*)&Bs[buf ^ 1][b_row][b_col] = bpre;
        }
        __syncthreads();
        buf ^= 1;
    }

    // Epilogue: add bias, write out
    float bcol[8];
#pragma unroll
    for (int j = 0; j < 4; j++) {
        bcol[j]     = bias[bn + tx * 4 + j];
        bcol[4 + j] = bias[bn + 64 + tx * 4 + j];
    }
#pragma unroll
    for (int rh = 0; rh < 2; rh++) {
#pragma unroll
        for (int i = 0; i < 4; i++) {
            const int row = bm + rh * 64 + ty * 4 + i;
#pragma unroll
            for (int ch = 0; ch < 2; ch++) {
                float4 o;
                o.x = acc[rh * 4 + i][ch * 4 + 0] + bcol[ch * 4 + 0];
                o.y = acc[rh * 4 + i][ch * 4 + 1] + bcol[ch * 4 + 1];
                o.z = acc[rh * 4 + i][ch * 4 + 2] + bcol[ch * 4 + 2];
                o.w = acc[rh * 4 + i][ch * 4 + 3] + bcol[ch * 4 + 3];
                *(float4*)(C + (size_t)row * N + bn + ch * 64 + tx * 4) = o;
            }
        }
    }
}

// ---------------------------------------------------------------------------
// Sparse local-window attention with relative position bias.
// One block = (128 queries, one head, one batch). Key window of 256 keys
// (covers [t0-64, t0+191]) staged in SMEM, dim-major with pad 257 so both
// the transposing stores and the per-key reads are bank-conflict-free.
// Each thread owns one query; softmax without max-subtraction (scores are
// provably small for this distribution: |s| < ~6).
// ---------------------------------------------------------------------------
#define QT   128
#define KW   256
#define KPAD 257

__global__ __launch_bounds__(128) void attn_kernel(
    const float* __restrict__ Q, const float* __restrict__ Kp,
    const float* __restrict__ Vp, const float* __restrict__ rel,
    float* __restrict__ O)
{
    extern __shared__ float sm[];
    float* Ks     = sm;                  // [DK][KPAD]
    float* Vs     = sm + DK * KPAD;      // [DK][KPAD]
    float* bias_s = sm + 2 * DK * KPAD;  // [129]

    const int t0  = blockIdx.x * QT;
    const int h   = blockIdx.y;
    const int b   = blockIdx.z;
    const int tid = threadIdx.x;
    const int base = t0 - WIN;

    const float* Kg = Kp + ((size_t)b * T_SEQ) * D_MODEL + h * DK;
    const float* Vg = Vp + ((size_t)b * T_SEQ) * D_MODEL + h * DK;

    // Stage K/V window (transpose to dim-major). 4096 float4s over 128 threads.
#pragma unroll
    for (int it = 0; it < (KW * DK / 4) / 128; it++) {
        const int idx4 = tid + it * 128;
        const int key  = idx4 >> 4;   // 0..255
        const int d4   = idx4 & 15;   // 0..15
        const int t    = base + key;
        float4 kv = make_float4(0.f, 0.f, 0.f, 0.f);
        float4 vv = make_float4(0.f, 0.f, 0.f, 0.f);
        if (t >= 0 && t < T_SEQ) {
            kv = *(const float4*)(Kg + (size_t)t * D_MODEL + d4 * 4);
            vv = *(const float4*)(Vg + (size_t)t * D_MODEL + d4 * 4);
        }
        Ks[(d4 * 4 + 0) * KPAD + key] = kv.x;
        Ks[(d4 * 4 + 1) * KPAD + key] = kv.y;
        Ks[(d4 * 4 + 2) * KPAD + key] = kv.z;
        Ks[(d4 * 4 + 3) * KPAD + key] = kv.w;
        Vs[(d4 * 4 + 0) * KPAD + key] = vv.x;
        Vs[(d4 * 4 + 1) * KPAD + key] = vv.y;
        Vs[(d4 * 4 + 2) * KPAD + key] = vv.z;
        Vs[(d4 * 4 + 3) * KPAD + key] = vv.w;
    }
    // Relative-position bias for this head: offset j-64 in [-64,64]
    for (int j = tid; j < 2 * WIN + 1; j += 128)
        bias_s[j] = rel[(size_t)(j + MAXD - WIN) * H_HEADS + h];
    __syncthreads();

    const int tq = t0 + tid;
    const float* qrow = Q + (size_t)(b * T_SEQ + tq) * D_MODEL + h * DK;
    float qv[DK];
#pragma unroll
    for (int i = 0; i < 16; i++) {
        float4 v = ((const float4*)qrow)[i];
        qv[4 * i + 0] = v.x; qv[4 * i + 1] = v.y;
        qv[4 * i + 2] = v.z; qv[4 * i + 3] = v.w;
    }

    float acc[DK];
#pragma unroll
    for (int d = 0; d < DK; d++) acc[d] = 0.f;
    float lsum = 0.f;

    int lo = tq - WIN; if (lo < 0) lo = 0;
    int hi = tq + WIN; if (hi > T_SEQ - 1) hi = T_SEQ - 1;

    for (int t = lo; t <= hi; t++) {
        const int key = t - base;
        float s0 = 0.f, s1 = 0.f, s2 = 0.f, s3 = 0.f;
#pragma unroll
        for (int d = 0; d < DK; d += 4) {
            s0 += qv[d + 0] * Ks[(d + 0) * KPAD + key];
            s1 += qv[d + 1] * Ks[(d + 1) * KPAD + key];
            s2 += qv[d + 2] * Ks[(d + 2) * KPAD + key];
            s3 += qv[d + 3] * Ks[(d + 3) * KPAD + key];
        }
        float s = ((s0 + s1) + (s2 + s3)) * 0.125f + bias_s[t - tq + WIN];
        const float e = __expf(s);
        lsum += e;
#pragma unroll
        for (int d = 0; d < DK; d++)
            acc[d] += e * Vs[d * KPAD + key];
    }

    const float inv = 1.0f / lsum;
    float* orow = O + (size_t)(b * T_SEQ + tq) * D_MODEL + h * DK;
#pragma unroll
    for (int i = 0; i < 16; i++) {
        float4 o;
        o.x = acc[4 * i + 0] * inv; o.y = acc[4 * i + 1] * inv;
        o.z = acc[4 * i + 2] * inv; o.w = acc[4 * i + 3] * inv;
        ((float4*)orow)[i] = o;
    }
}

// ---------------------------------------------------------------------------
// Launch
// ---------------------------------------------------------------------------
extern "C" void kernel_launch(void* const* d_in, const int* in_sizes, int n_in,
                              void* d_out, int out_size)
{
    const float* q_in = (const float*)d_in[0];
    const float* k_in = (const float*)d_in[1];
    const float* v_in = (const float*)d_in[2];
    const float* Wq   = (const float*)d_in[3];
    const float* bq   = (const float*)d_in[4];
    const float* Wk   = (const float*)d_in[5];
    const float* bk   = (const float*)d_in[6];
    const float* Wv   = (const float*)d_in[7];
    const float* bv   = (const float*)d_in[8];
    const float* Wo   = (const float*)d_in[9];
    const float* bo   = (const float*)d_in[10];
    const float* rel  = (const float*)d_in[11];
    float* out = (float*)d_out;

    float *pQ, *pK, *pV, *pA;
    cudaGetSymbolAddress((void**)&pQ, g_Q);
    cudaGetSymbolAddress((void**)&pK, g_K);
    cudaGetSymbolAddress((void**)&pV, g_V);
    cudaGetSymbolAddress((void**)&pA, g_A);

    dim3 ggrid(D_MODEL / BN, M_ROWS / BM);

    sgemm_bias<<<ggrid, 256>>>(q_in, Wq, bq, pQ);
    sgemm_bias<<<ggrid, 256>>>(k_in, Wk, bk, pK);
    sgemm_bias<<<ggrid, 256>>>(v_in, Wv, bv, pV);

    const size_t ATTN_SMEM = (size_t)(2 * DK * KPAD + 2 * WIN + 1) * sizeof(float);
    cudaFuncSetAttribute(attn_kernel, cudaFuncAttributeMaxDynamicSharedMemorySize,
                         (int)ATTN_SMEM);
    attn_kernel<<<dim3(T_SEQ / QT, H_HEADS, B_SZ), 128, ATTN_SMEM>>>(pQ, pK, pV, rel, pA);

    sgemm_bias<<<ggrid, 256>>>(pA, Wo, bo, out);
}

// round 3
// speedup vs baseline: 2.0508x; 2.0508x over previous
#include <cuda_runtime.h>
#include <cstdint>

// Problem constants
#define B_SZ    2
#define T_SEQ   2048
#define D_MODEL 1024
#define H_HEADS 16
#define DK      64
#define M_ROWS  (B_SZ * T_SEQ)   // 4096
#define WIN     64
#define MAXD    128

// ---------------------------------------------------------------------------
// Scratch (device globals: allocation-free per harness rules)
// ---------------------------------------------------------------------------
__device__ float g_Q[(size_t)M_ROWS * D_MODEL];
__device__ float g_K[(size_t)M_ROWS * D_MODEL];
__device__ float g_V[(size_t)M_ROWS * D_MODEL];
__device__ float g_A[(size_t)M_ROWS * D_MODEL];

// ---------------------------------------------------------------------------
// tf32 tensor-core GEMM: C[M x N] = A[M x K] @ B[K x N] + bias[N]
// 128x128 block tile, BK=32, 256 threads (8 warps as 2m x 4n, warp tile 64x32),
// mma.sync.m16n8k8 tf32, double-buffered SMEM, all SMEM accesses
// bank-conflict-free by construction:
//   As stride 36 floats -> frag bank = (4*g + tg) mod 32  (bijective)
//   Bs stride 136 floats -> frag bank = (8*tg + g) mod 32 (bijective)
// ---------------------------------------------------------------------------
#define GBM 128
#define GBN 128
#define GBK 32
#define ASTRIDE 36      // 32 + 4
#define BSTRIDE 136     // 128 + 8
#define ABUF (128 * ASTRIDE)   // 4608 floats per buffer
#define BBUF (32 * BSTRIDE)    // 4352 floats per buffer
#define GEMM_SMEM ((2 * ABUF + 2 * BBUF) * sizeof(float))  // 71680 B

__device__ __forceinline__ float f2tf(float x) {
    unsigned r;
    asm("cvt.rna.tf32.f32 %0, %1;" : "=r"(r) : "f"(x));
    return __uint_as_float(r);
}

__device__ __forceinline__ void mma_tf32(float* c, const unsigned* a, const unsigned* b) {
    asm volatile(
        "mma.sync.aligned.m16n8k8.row.col.f32.tf32.tf32.f32 "
        "{%0,%1,%2,%3}, {%4,%5,%6,%7}, {%8,%9}, {%0,%1,%2,%3};\n"
        : "+f"(c[0]), "+f"(c[1]), "+f"(c[2]), "+f"(c[3])
        : "r"(a[0]), "r"(a[1]), "r"(a[2]), "r"(a[3]), "r"(b[0]), "r"(b[1]));
}

__global__ __launch_bounds__(256) void tgemm_bias(
    const float* __restrict__ A, const float* __restrict__ Bm,
    const float* __restrict__ bias, float* __restrict__ C)
{
    extern __shared__ float sh[];
    float* As = sh;               // [2][128][ASTRIDE]
    float* Bs = sh + 2 * ABUF;    // [2][32][BSTRIDE]

    const int N = D_MODEL, K = D_MODEL;
    const int tid  = threadIdx.x;
    const int bm   = blockIdx.y * GBM;
    const int bn   = blockIdx.x * GBN;
    const int warp = tid >> 5, lane = tid & 31;
    const int wm = warp & 1;        // 0..1 -> 64-row slab
    const int wn = warp >> 1;       // 0..3 -> 32-col slab
    const int g  = lane >> 2;       // groupID 0..7
    const int tg = lane & 3;        // threadID-in-group 0..3

    // Loader mapping (i = 0..3 sub-iterations, idx = tid + i*256):
    const int arow0 = tid >> 3, ac4 = tid & 7;    // A: row = arow0+32i, col4 = ac4
    const int brow0 = tid >> 5, bc4 = tid & 31;   // B: row = brow0+8i,  col4 = bc4

    float acc[4][4][4];
#pragma unroll
    for (int mi = 0; mi < 4; mi++)
#pragma unroll
        for (int nj = 0; nj < 4; nj++)
#pragma unroll
            for (int r = 0; r < 4; r++) acc[mi][nj][r] = 0.f;

    // ---- stage panel 0 ----
#pragma unroll
    for (int i = 0; i < 4; i++) {
        float4 v = *(const float4*)(A + (size_t)(bm + arow0 + 32 * i) * K + ac4 * 4);
        float4 t = make_float4(f2tf(v.x), f2tf(v.y), f2tf(v.z), f2tf(v.w));
        *(float4*)&As[(arow0 + 32 * i) * ASTRIDE + ac4 * 4] = t;
        float4 w = *(const float4*)(Bm + (size_t)(brow0 + 8 * i) * N + bn + bc4 * 4);
        float4 u = make_float4(f2tf(w.x), f2tf(w.y), f2tf(w.z), f2tf(w.w));
        *(float4*)&Bs[(brow0 + 8 * i) * BSTRIDE + bc4 * 4] = u;
    }
    __syncthreads();

    int buf = 0;
    for (int kp = 0; kp < K; kp += GBK) {
        // prefetch next panel into registers
        float4 ar[4], br[4];
        const bool has_next = (kp + GBK) < K;
        if (has_next) {
#pragma unroll
            for (int i = 0; i < 4; i++) {
                ar[i] = *(const float4*)(A + (size_t)(bm + arow0 + 32 * i) * K + (kp + GBK) + ac4 * 4);
                br[i] = *(const float4*)(Bm + (size_t)(kp + GBK + brow0 + 8 * i) * N + bn + bc4 * 4);
            }
        }

        const float* Ab = As + buf * ABUF;
        const float* Bb = Bs + buf * BBUF;
#pragma unroll
        for (int ks = 0; ks < 4; ks++) {
            unsigned a[4][4], b[4][2];
#pragma unroll
            for (int mi = 0; mi < 4; mi++) {
                const int m0 = wm * 64 + mi * 16 + g;
                const int k0 = ks * 8 + tg;
                a[mi][0] = __float_as_uint(Ab[(m0)     * ASTRIDE + k0]);
                a[mi][1] = __float_as_uint(Ab[(m0 + 8) * ASTRIDE + k0]);
                a[mi][2] = __float_as_uint(Ab[(m0)     * ASTRIDE + k0 + 4]);
                a[mi][3] = __float_as_uint(Ab[(m0 + 8) * ASTRIDE + k0 + 4]);
            }
#pragma unroll
            for (int nj = 0; nj < 4; nj++) {
                const int n0 = wn * 32 + nj * 8 + g;
                const int k0 = ks * 8 + tg;
                b[nj][0] = __float_as_uint(Bb[(k0)     * BSTRIDE + n0]);
                b[nj][1] = __float_as_uint(Bb[(k0 + 4) * BSTRIDE + n0]);
            }
#pragma unroll
            for (int mi = 0; mi < 4; mi++)
#pragma unroll
                for (int nj = 0; nj < 4; nj++)
                    mma_tf32(acc[mi][nj], a[mi], b[nj]);
        }

        if (has_next) {
            float* An = As + (buf ^ 1) * ABUF;
            float* Bn = Bs + (buf ^ 1) * BBUF;
#pragma unroll
            for (int i = 0; i < 4; i++) {
                float4 t = make_float4(f2tf(ar[i].x), f2tf(ar[i].y), f2tf(ar[i].z), f2tf(ar[i].w));
                *(float4*)&An[(arow0 + 32 * i) * ASTRIDE + ac4 * 4] = t;
                float4 u = make_float4(f2tf(br[i].x), f2tf(br[i].y), f2tf(br[i].z), f2tf(br[i].w));
                *(float4*)&Bn[(brow0 + 8 * i) * BSTRIDE + bc4 * 4] = u;
            }
        }
        __syncthreads();
        buf ^= 1;
    }

    // ---- epilogue: add bias, write C ----
#pragma unroll
    for (int nj = 0; nj < 4; nj++) {
        const int col = bn + wn * 32 + nj * 8 + tg * 2;
        const float2 bv = *(const float2*)&bias[col];
#pragma unroll
        for (int mi = 0; mi < 4; mi++) {
            const int row0 = bm + wm * 64 + mi * 16 + g;
            float2 o0, o1;
            o0.x = acc[mi][nj][0] + bv.x;
            o0.y = acc[mi][nj][1] + bv.y;
            o1.x = acc[mi][nj][2] + bv.x;
            o1.y = acc[mi][nj][3] + bv.y;
            *(float2*)(C + (size_t)row0 * N + col)       = o0;
            *(float2*)(C + (size_t)(row0 + 8) * N + col) = o1;
        }
    }
}

// ---------------------------------------------------------------------------
// Sparse local-window attention with relative position bias (unchanged from R1).
// One block = (128 queries, one head, one batch). Key window of 256 keys
// staged dim-major in SMEM with pad 257 (conflict-free).
// ---------------------------------------------------------------------------
#define QT   128
#define KW   256
#define KPAD 257

__global__ __launch_bounds__(128) void attn_kernel(
    const float* __restrict__ Q, const float* __restrict__ Kp,
    const float* __restrict__ Vp, const float* __restrict__ rel,
    float* __restrict__ O)
{
    extern __shared__ float sm[];
    float* Ks     = sm;                  // [DK][KPAD]
    float* Vs     = sm + DK * KPAD;      // [DK][KPAD]
    float* bias_s = sm + 2 * DK * KPAD;  // [129]

    const int t0  = blockIdx.x * QT;
    const int h   = blockIdx.y;
    const int b   = blockIdx.z;
    const int tid = threadIdx.x;
    const int base = t0 - WIN;

    const float* Kg = Kp + ((size_t)b * T_SEQ) * D_MODEL + h * DK;
    const float* Vg = Vp + ((size_t)b * T_SEQ) * D_MODEL + h * DK;

#pragma unroll
    for (int it = 0; it < (KW * DK / 4) / 128; it++) {
        const int idx4 = tid + it * 128;
        const int key  = idx4 >> 4;
        const int d4   = idx4 & 15;
        const int t    = base + key;
        float4 kv = make_float4(0.f, 0.f, 0.f, 0.f);
        float4 vv = make_float4(0.f, 0.f, 0.f, 0.f);
        if (t >= 0 && t < T_SEQ) {
            kv = *(const float4*)(Kg + (size_t)t * D_MODEL + d4 * 4);
            vv = *(const float4*)(Vg + (size_t)t * D_MODEL + d4 * 4);
        }
        Ks[(d4 * 4 + 0) * KPAD + key] = kv.x;
        Ks[(d4 * 4 + 1) * KPAD + key] = kv.y;
        Ks[(d4 * 4 + 2) * KPAD + key] = kv.z;
        Ks[(d4 * 4 + 3) * KPAD + key] = kv.w;
        Vs[(d4 * 4 + 0) * KPAD + key] = vv.x;
        Vs[(d4 * 4 + 1) * KPAD + key] = vv.y;
        Vs[(d4 * 4 + 2) * KPAD + key] = vv.z;
        Vs[(d4 * 4 + 3) * KPAD + key] = vv.w;
    }
    for (int j = tid; j < 2 * WIN + 1; j += 128)
        bias_s[j] = rel[(size_t)(j + MAXD - WIN) * H_HEADS + h];
    __syncthreads();

    const int tq = t0 + tid;
    const float* qrow = Q + (size_t)(b * T_SEQ + tq) * D_MODEL + h * DK;
    float qv[DK];
#pragma unroll
    for (int i = 0; i < 16; i++) {
        float4 v = ((const float4*)qrow)[i];
        qv[4 * i + 0] = v.x; qv[4 * i + 1] = v.y;
        qv[4 * i + 2] = v.z; qv[4 * i + 3] = v.w;
    }

    float acc[DK];
#pragma unroll
    for (int d = 0; d < DK; d++) acc[d] = 0.f;
    float lsum = 0.f;

    int lo = tq - WIN; if (lo < 0) lo = 0;
    int hi = tq + WIN; if (hi > T_SEQ - 1) hi = T_SEQ - 1;

    for (int t = lo; t <= hi; t++) {
        const int key = t - base;
        float s0 = 0.f, s1 = 0.f, s2 = 0.f, s3 = 0.f;
#pragma unroll
        for (int d = 0; d < DK; d += 4) {
            s0 += qv[d + 0] * Ks[(d + 0) * KPAD + key];
            s1 += qv[d + 1] * Ks[(d + 1) * KPAD + key];
            s2 += qv[d + 2] * Ks[(d + 2) * KPAD + key];
            s3 += qv[d + 3] * Ks[(d + 3) * KPAD + key];
        }
        float s = ((s0 + s1) + (s2 + s3)) * 0.125f + bias_s[t - tq + WIN];
        const float e = __expf(s);
        lsum += e;
#pragma unroll
        for (int d = 0; d < DK; d++)
            acc[d] += e * Vs[d * KPAD + key];
    }

    const float inv = 1.0f / lsum;
    float* orow = O + (size_t)(b * T_SEQ + tq) * D_MODEL + h * DK;
#pragma unroll
    for (int i = 0; i < 16; i++) {
        float4 o;
        o.x = acc[4 * i + 0] * inv; o.y = acc[4 * i + 1] * inv;
        o.z = acc[4 * i + 2] * inv; o.w = acc[4 * i + 3] * inv;
        ((float4*)orow)[i] = o;
    }
}

// ---------------------------------------------------------------------------
// Launch
// ---------------------------------------------------------------------------
extern "C" void kernel_launch(void* const* d_in, const int* in_sizes, int n_in,
                              void* d_out, int out_size)
{
    const float* q_in = (const float*)d_in[0];
    const float* k_in = (const float*)d_in[1];
    const float* v_in = (const float*)d_in[2];
    const float* Wq   = (const float*)d_in[3];
    const float* bq   = (const float*)d_in[4];
    const float* Wk   = (const float*)d_in[5];
    const float* bk   = (const float*)d_in[6];
    const float* Wv   = (const float*)d_in[7];
    const float* bv   = (const float*)d_in[8];
    const float* Wo   = (const float*)d_in[9];
    const float* bo   = (const float*)d_in[10];
    const float* rel  = (const float*)d_in[11];
    float* out = (float*)d_out;

    float *pQ, *pK, *pV, *pA;
    cudaGetSymbolAddress((void**)&pQ, g_Q);
    cudaGetSymbolAddress((void**)&pK, g_K);
    cudaGetSymbolAddress((void**)&pV, g_V);
    cudaGetSymbolAddress((void**)&pA, g_A);

    cudaFuncSetAttribute(tgemm_bias, cudaFuncAttributeMaxDynamicSharedMemorySize,
                         (int)GEMM_SMEM);

    dim3 ggrid(D_MODEL / GBN, M_ROWS / GBM);

    tgemm_bias<<<ggrid, 256, GEMM_SMEM>>>(q_in, Wq, bq, pQ);
    tgemm_bias<<<ggrid, 256, GEMM_SMEM>>>(k_in, Wk, bk, pK);
    tgemm_bias<<<ggrid, 256, GEMM_SMEM>>>(v_in, Wv, bv, pV);

    const size_t ATTN_SMEM = (size_t)(2 * DK * KPAD + 2 * WIN + 1) * sizeof(float);
    cudaFuncSetAttribute(attn_kernel, cudaFuncAttributeMaxDynamicSharedMemorySize,
                         (int)ATTN_SMEM);
    attn_kernel<<<dim3(T_SEQ / QT, H_HEADS, B_SZ), 128, ATTN_SMEM>>>(pQ, pK, pV, rel, pA);

    tgemm_bias<<<ggrid, 256, GEMM_SMEM>>>(pA, Wo, bo, out);
}

// round 5
// speedup vs baseline: 2.7560x; 1.3439x over previous
#include <cuda_runtime.h>
#include <cstdint>

// Problem constants
#define B_SZ    2
#define T_SEQ   2048
#define D_MODEL 1024
#define H_HEADS 16
#define DK      64
#define M_ROWS  (B_SZ * T_SEQ)   // 4096
#define WIN     64
#define MAXD    128

// ---------------------------------------------------------------------------
// Scratch
// ---------------------------------------------------------------------------
__device__ float g_Q[(size_t)M_ROWS * D_MODEL];
__device__ float g_K[(size_t)M_ROWS * D_MODEL];
__device__ float g_V[(size_t)M_ROWS * D_MODEL];
__device__ float g_A[(size_t)M_ROWS * D_MODEL];

__device__ __forceinline__ float f2tf(float x) {
    unsigned r;
    asm("cvt.rna.tf32.f32 %0, %1;" : "=r"(r) : "f"(x));
    return __uint_as_float(r);
}

__device__ __forceinline__ void mma_tf32(float* c, const unsigned* a, const unsigned* b) {
    asm volatile(
        "mma.sync.aligned.m16n8k8.row.col.f32.tf32.tf32.f32 "
        "{%0,%1,%2,%3}, {%4,%5,%6,%7}, {%8,%9}, {%0,%1,%2,%3};\n"
        : "+f"(c[0]), "+f"(c[1]), "+f"(c[2]), "+f"(c[3])
        : "r"(a[0]), "r"(a[1]), "r"(a[2]), "r"(a[3]), "r"(b[0]), "r"(b[1]));
}

// ---------------------------------------------------------------------------
// tf32 tensor-core GEMM (unchanged from R3 — passing at ~70us each)
// ---------------------------------------------------------------------------
#define GBM 128
#define GBN 128
#define GBK 32
#define ASTRIDE 36
#define BSTRIDE 136
#define ABUF (128 * ASTRIDE)
#define BBUF (32 * BSTRIDE)
#define GEMM_SMEM ((2 * ABUF + 2 * BBUF) * sizeof(float))

__global__ __launch_bounds__(256) void tgemm_bias(
    const float* __restrict__ A, const float* __restrict__ Bm,
    const float* __restrict__ bias, float* __restrict__ C)
{
    extern __shared__ float sh[];
    float* As = sh;
    float* Bs = sh + 2 * ABUF;

    const int N = D_MODEL, K = D_MODEL;
    const int tid  = threadIdx.x;
    const int bm   = blockIdx.y * GBM;
    const int bn   = blockIdx.x * GBN;
    const int warp = tid >> 5, lane = tid & 31;
    const int wm = warp & 1;
    const int wn = warp >> 1;
    const int g  = lane >> 2;
    const int tg = lane & 3;

    const int arow0 = tid >> 3, ac4 = tid & 7;
    const int brow0 = tid >> 5, bc4 = tid & 31;

    float acc[4][4][4];
#pragma unroll
    for (int mi = 0; mi < 4; mi++)
#pragma unroll
        for (int nj = 0; nj < 4; nj++)
#pragma unroll
            for (int r = 0; r < 4; r++) acc[mi][nj][r] = 0.f;

#pragma unroll
    for (int i = 0; i < 4; i++) {
        float4 v = *(const float4*)(A + (size_t)(bm + arow0 + 32 * i) * K + ac4 * 4);
        float4 t = make_float4(f2tf(v.x), f2tf(v.y), f2tf(v.z), f2tf(v.w));
        *(float4*)&As[(arow0 + 32 * i) * ASTRIDE + ac4 * 4] = t;
        float4 w = *(const float4*)(Bm + (size_t)(brow0 + 8 * i) * N + bn + bc4 * 4);
        float4 u = make_float4(f2tf(w.x), f2tf(w.y), f2tf(w.z), f2tf(w.w));
        *(float4*)&Bs[(brow0 + 8 * i) * BSTRIDE + bc4 * 4] = u;
    }
    __syncthreads();

    int buf = 0;
    for (int kp = 0; kp < K; kp += GBK) {
        float4 ar[4], br[4];
        const bool has_next = (kp + GBK) < K;
        if (has_next) {
#pragma unroll
            for (int i = 0; i < 4; i++) {
                ar[i] = *(const float4*)(A + (size_t)(bm + arow0 + 32 * i) * K + (kp + GBK) + ac4 * 4);
                br[i] = *(const float4*)(Bm + (size_t)(kp + GBK + brow0 + 8 * i) * N + bn + bc4 * 4);
            }
        }

        const float* Ab = As + buf * ABUF;
        const float* Bb = Bs + buf * BBUF;
#pragma unroll
        for (int ks = 0; ks < 4; ks++) {
            unsigned a[4][4], b[4][2];
#pragma unroll
            for (int mi = 0; mi < 4; mi++) {
                const int m0 = wm * 64 + mi * 16 + g;
                const int k0 = ks * 8 + tg;
                a[mi][0] = __float_as_uint(Ab[(m0)     * ASTRIDE + k0]);
                a[mi][1] = __float_as_uint(Ab[(m0 + 8) * ASTRIDE + k0]);
                a[mi][2] = __float_as_uint(Ab[(m0)     * ASTRIDE + k0 + 4]);
                a[mi][3] = __float_as_uint(Ab[(m0 + 8) * ASTRIDE + k0 + 4]);
            }
#pragma unroll
            for (int nj = 0; nj < 4; nj++) {
                const int n0 = wn * 32 + nj * 8 + g;
                const int k0 = ks * 8 + tg;
                b[nj][0] = __float_as_uint(Bb[(k0)     * BSTRIDE + n0]);
                b[nj][1] = __float_as_uint(Bb[(k0 + 4) * BSTRIDE + n0]);
            }
#pragma unroll
            for (int mi = 0; mi < 4; mi++)
#pragma unroll
                for (int nj = 0; nj < 4; nj++)
                    mma_tf32(acc[mi][nj], a[mi], b[nj]);
        }

        if (has_next) {
            float* An = As + (buf ^ 1) * ABUF;
            float* Bn = Bs + (buf ^ 1) * BBUF;
#pragma unroll
            for (int i = 0; i < 4; i++) {
                float4 t = make_float4(f2tf(ar[i].x), f2tf(ar[i].y), f2tf(ar[i].z), f2tf(ar[i].w));
                *(float4*)&An[(arow0 + 32 * i) * ASTRIDE + ac4 * 4] = t;
                float4 u = make_float4(f2tf(br[i].x), f2tf(br[i].y), f2tf(br[i].z), f2tf(br[i].w));
                *(float4*)&Bn[(brow0 + 8 * i) * BSTRIDE + bc4 * 4] = u;
            }
        }
        __syncthreads();
        buf ^= 1;
    }

#pragma unroll
    for (int nj = 0; nj < 4; nj++) {
        const int col = bn + wn * 32 + nj * 8 + tg * 2;
        const float2 bv = *(const float2*)&bias[col];
#pragma unroll
        for (int mi = 0; mi < 4; mi++) {
            const int row0 = bm + wm * 64 + mi * 16 + g;
            float2 o0, o1;
            o0.x = acc[mi][nj][0] + bv.x;
            o0.y = acc[mi][nj][1] + bv.y;
            o1.x = acc[mi][nj][2] + bv.x;
            o1.y = acc[mi][nj][3] + bv.y;
            *(float2*)(C + (size_t)row0 * N + col)       = o0;
            *(float2*)(C + (size_t)(row0 + 8) * N + col) = o1;
        }
    }
}

// ---------------------------------------------------------------------------
// Tensor-core sparse local-window attention.
// Block = (128 queries, 1 head, 1 batch); 256 threads = 8 warps; warp owns 16
// query rows. 256-key window staged once (tf32, row-major, coalesced).
// Per 64-key chunk: S = Q@K^T (mma tf32), bias+mask+exp in C-layout, P via
// per-warp SMEM, O += P@V. All fragment LDS bank-conflict-free:
//   Ks stride 68: bank = 4g+tg (bijective)   [B-frag of S]
//   Vs stride 72: bank = 8tg+g (bijective)   [B-frag of PV, row-major!]
//   Ps stride 68: bank = 4g+tg (bijective)   [A-frag of PV]
// ---------------------------------------------------------------------------
#define AKSTR 68
#define AVSTR 72
#define APSTR 68
#define AKS_F (256 * AKSTR)
#define AVS_F (256 * AVSTR)
#define APS_F (8 * 16 * APSTR)
#define ATTN_SMEM_B ((AKS_F + AVS_F + APS_F + 132) * sizeof(float))

__global__ __launch_bounds__(256) void attn_mma(
    const float* __restrict__ Q, const float* __restrict__ Kp,
    const float* __restrict__ Vp, const float* __restrict__ rel,
    float* __restrict__ O)
{
    extern __shared__ float sm[];
    float* Ks = sm;
    float* Vs = sm + AKS_F;
    float* Ps = sm + AKS_F + AVS_F;
    float* bs = sm + AKS_F + AVS_F + APS_F;

    const int t0   = blockIdx.x * 128;
    const int h    = blockIdx.y;
    const int b    = blockIdx.z;
    const int base = t0 - WIN;
    const int tid  = threadIdx.x;
    const int warp = tid >> 5, lane = tid & 31;
    const int g = lane >> 2, tg = lane & 3;

    const float* Kg = Kp + (size_t)b * T_SEQ * D_MODEL + h * DK;
    const float* Vg = Vp + (size_t)b * T_SEQ * D_MODEL + h * DK;

    // Stage 256-key K/V window (row-major, converted to tf32). Coalesced LDG,
    // conflict-free STS.128 (strides 68/72 floats = 17/18 x 16B).
#pragma unroll
    for (int it = 0; it < 16; it++) {
        const int idx = tid + it * 256;
        const int key = idx >> 4, d4 = idx & 15;
        const int t   = base + key;
        float4 kv = make_float4(0.f, 0.f, 0.f, 0.f);
        float4 vv = make_float4(0.f, 0.f, 0.f, 0.f);
        if (t >= 0 && t < T_SEQ) {
            kv = *(const float4*)(Kg + (size_t)t * D_MODEL + d4 * 4);
            vv = *(const float4*)(Vg + (size_t)t * D_MODEL + d4 * 4);
        }
        *(float4*)&Ks[key * AKSTR + d4 * 4] =
            make_float4(f2tf(kv.x), f2tf(kv.y), f2tf(kv.z), f2tf(kv.w));
        *(float4*)&Vs[key * AVSTR + d4 * 4] =
            make_float4(f2tf(vv.x), f2tf(vv.y), f2tf(vv.z), f2tf(vv.w));
    }
    if (tid < 2 * WIN + 1)
        bs[tid] = rel[(size_t)(tid + MAXD - WIN) * H_HEADS + h];

    // Q fragments: registers for the whole kernel (one-time strided LDG)
    const int q0 = t0 + warp * 16;
    const float* Qg = Q + (size_t)(b * T_SEQ + q0) * D_MODEL + h * DK;
    unsigned qa[8][4];
#pragma unroll
    for (int kt = 0; kt < 8; kt++) {
        qa[kt][0] = __float_as_uint(f2tf(Qg[(size_t)g       * D_MODEL + kt * 8 + tg]));
        qa[kt][1] = __float_as_uint(f2tf(Qg[(size_t)(g + 8) * D_MODEL + kt * 8 + tg]));
        qa[kt][2] = __float_as_uint(f2tf(Qg[(size_t)g       * D_MODEL + kt * 8 + tg + 4]));
        qa[kt][3] = __float_as_uint(f2tf(Qg[(size_t)(g + 8) * D_MODEL + kt * 8 + tg + 4]));
    }
    __syncthreads();

    float oacc[8][4];
#pragma unroll
    for (int nt = 0; nt < 8; nt++)
#pragma unroll
        for (int r = 0; r < 4; r++) oacc[nt][r] = 0.f;
    float rs0 = 0.f, rs1 = 0.f;
    float* Pw = Ps + warp * 16 * APSTR;

#pragma unroll 1
    for (int c = 0; c < 4; c++) {
        // ---- S = Q @ K_chunk^T (16 x 64 per warp) ----
        float sacc[8][4];
#pragma unroll
        for (int nt = 0; nt < 8; nt++)
#pragma unroll
            for (int r = 0; r < 4; r++) sacc[nt][r] = 0.f;
#pragma unroll
        for (int nt = 0; nt < 8; nt++) {
            const float* kb = Ks + (size_t)(c * 64 + nt * 8 + g) * AKSTR + tg;
#pragma unroll
            for (int kt = 0; kt < 8; kt++) {
                unsigned bf[2];
                bf[0] = __float_as_uint(kb[kt * 8]);
                bf[1] = __float_as_uint(kb[kt * 8 + 4]);
                mma_tf32(sacc[nt], qa[kt], bf);
            }
        }

        // ---- bias + band mask + exp; stage P (tf32) ----
        __syncwarp();
#pragma unroll
        for (int nt = 0; nt < 8; nt++) {
            const int col = c * 64 + nt * 8 + 2 * tg;
            const int tk  = base + col;
            const int d0  = tk - (q0 + g);        // row g
            const int d2  = tk - (q0 + 8 + g);    // row g+8
            float e0 = 0.f, e1 = 0.f, e2 = 0.f, e3 = 0.f;
            if (tk >= 0 && tk < T_SEQ) {
                if (d0 >= -WIN && d0 <= WIN) e0 = __expf(sacc[nt][0] * 0.125f + bs[d0 + WIN]);
                if (d2 >= -WIN && d2 <= WIN) e2 = __expf(sacc[nt][2] * 0.125f + bs[d2 + WIN]);
            }
            if (tk + 1 >= 0 && tk + 1 < T_SEQ) {
                if (d0 + 1 >= -WIN && d0 + 1 <= WIN) e1 = __expf(sacc[nt][1] * 0.125f + bs[d0 + 1 + WIN]);
                if (d2 + 1 >= -WIN && d2 + 1 <= WIN) e3 = __expf(sacc[nt][3] * 0.125f + bs[d2 + 1 + WIN]);
            }
            rs0 += e0 + e1;
            rs1 += e2 + e3;
            *(float2*)&Pw[(size_t)g       * APSTR + nt * 8 + 2 * tg] = make_float2(f2tf(e0), f2tf(e1));
            *(float2*)&Pw[(size_t)(g + 8) * APSTR + nt * 8 + 2 * tg] = make_float2(f2tf(e2), f2tf(e3));
        }
        __syncwarp();

        // ---- O += P_chunk (16x64) @ V_chunk (64x64) ----
#pragma unroll
        for (int kt = 0; kt < 8; kt++) {
            unsigned pa[4];
            pa[0] = __float_as_uint(Pw[(size_t)g       * APSTR + kt * 8 + tg]);
            pa[1] = __float_as_uint(Pw[(size_t)(g + 8) * APSTR + kt * 8 + tg]);
            pa[2] = __float_as_uint(Pw[(size_t)g       * APSTR + kt * 8 + tg + 4]);
            pa[3] = __float_as_uint(Pw[(size_t)(g + 8) * APSTR + kt * 8 + tg + 4]);
            const float* vb = Vs + (size_t)(c * 64 + kt * 8 + tg) * AVSTR + g;
#pragma unroll
            for (int nt = 0; nt < 8; nt++) {
                unsigned bf[2];
                bf[0] = __float_as_uint(vb[nt * 8]);
                bf[1] = __float_as_uint(vb[4 * AVSTR + nt * 8]);
                mma_tf32(oacc[nt], pa, bf);
            }
        }
    }

    // ---- row sums (quad reduce) + normalize + store ----
    rs0 += __shfl_xor_sync(0xffffffffu, rs0, 1);
    rs0 += __shfl_xor_sync(0xffffffffu, rs0, 2);
    rs1 += __shfl_xor_sync(0xffffffffu, rs1, 1);
    rs1 += __shfl_xor_sync(0xffffffffu, rs1, 2);
    const float i0 = 1.f / rs0, i1 = 1.f / rs1;

    float* Og = O + (size_t)(b * T_SEQ + q0) * D_MODEL + h * DK;
#pragma unroll
    for (int nt = 0; nt < 8; nt++) {
        *(float2*)&Og[(size_t)g       * D_MODEL + nt * 8 + 2 * tg] =
            make_float2(oacc[nt][0] * i0, oacc[nt][1] * i0);
        *(float2*)&Og[(size_t)(g + 8) * D_MODEL + nt * 8 + 2 * tg] =
            make_float2(oacc[nt][2] * i1, oacc[nt][3] * i1);
    }
}

// ---------------------------------------------------------------------------
// Launch
// ---------------------------------------------------------------------------
extern "C" void kernel_launch(void* const* d_in, const int* in_sizes, int n_in,
                              void* d_out, int out_size)
{
    const float* q_in = (const float*)d_in[0];
    const float* k_in = (const float*)d_in[1];
    const float* v_in = (const float*)d_in[2];
    const float* Wq   = (const float*)d_in[3];
    const float* bq   = (const float*)d_in[4];
    const float* Wk   = (const float*)d_in[5];
    const float* bk   = (const float*)d_in[6];
    const float* Wv   = (const float*)d_in[7];
    const float* bv   = (const float*)d_in[8];
    const float* Wo   = (const float*)d_in[9];
    const float* bo   = (const float*)d_in[10];
    const float* rel  = (const float*)d_in[11];
    float* out = (float*)d_out;

    float *pQ, *pK, *pV, *pA;
    cudaGetSymbolAddress((void**)&pQ, g_Q);
    cudaGetSymbolAddress((void**)&pK, g_K);
    cudaGetSymbolAddress((void**)&pV, g_V);
    cudaGetSymbolAddress((void**)&pA, g_A);

    cudaFuncSetAttribute(tgemm_bias, cudaFuncAttributeMaxDynamicSharedMemorySize,
                         (int)GEMM_SMEM);
    cudaFuncSetAttribute(attn_mma, cudaFuncAttributeMaxDynamicSharedMemorySize,
                         (int)ATTN_SMEM_B);

    dim3 ggrid(D_MODEL / GBN, M_ROWS / GBM);

    tgemm_bias<<<ggrid, 256, GEMM_SMEM>>>(q_in, Wq, bq, pQ);
    tgemm_bias<<<ggrid, 256, GEMM_SMEM>>>(k_in, Wk, bk, pK);
    tgemm_bias<<<ggrid, 256, GEMM_SMEM>>>(v_in, Wv, bv, pV);

    attn_mma<<<dim3(T_SEQ / 128, H_HEADS, B_SZ), 256, ATTN_SMEM_B>>>(pQ, pK, pV, rel, pA);

    tgemm_bias<<<ggrid, 256, GEMM_SMEM>>>(pA, Wo, bo, out);
}

// round 7
// speedup vs baseline: 2.8677x; 1.0406x over previous
#include <cuda_runtime.h>
#include <cstdint>

// Problem constants
#define B_SZ    2
#define T_SEQ   2048
#define D_MODEL 1024
#define H_HEADS 16
#define DK      64
#define M_ROWS  (B_SZ * T_SEQ)   // 4096
#define WIN     64
#define MAXD    128

// ---------------------------------------------------------------------------
// Scratch
// ---------------------------------------------------------------------------
__device__ float g_Q[(size_t)M_ROWS * D_MODEL];
__device__ float g_K[(size_t)M_ROWS * D_MODEL];
__device__ float g_V[(size_t)M_ROWS * D_MODEL];
__device__ float g_A[(size_t)M_ROWS * D_MODEL];
__device__ float g_WR[(size_t)4 * D_MODEL * D_MODEL];   // tf32-rounded weights

__device__ __forceinline__ float f2tf(float x) {
    unsigned r;
    asm("cvt.rna.tf32.f32 %0, %1;" : "=r"(r) : "f"(x));
    return __uint_as_float(r);
}

__device__ __forceinline__ void mma_tf32(float* c, const unsigned* a, const unsigned* b) {
    asm volatile(
        "mma.sync.aligned.m16n8k8.row.col.f32.tf32.tf32.f32 "
        "{%0,%1,%2,%3}, {%4,%5,%6,%7}, {%8,%9}, {%0,%1,%2,%3};\n"
        : "+f"(c[0]), "+f"(c[1]), "+f"(c[2]), "+f"(c[3])
        : "r"(a[0]), "r"(a[1]), "r"(a[2]), "r"(a[3]), "r"(b[0]), "r"(b[1]));
}

__device__ __forceinline__ uint32_t smem_u32(const void* p) {
    uint32_t a;
    asm("{ .reg .u64 t; cvta.to.shared.u64 t, %1; cvt.u32.u64 %0, t; }" : "=r"(a) : "l"(p));
    return a;
}

__device__ __forceinline__ void cp16(uint32_t dst, const void* src) {
    asm volatile("cp.async.cg.shared.global [%0], [%1], 16;" :: "r"(dst), "l"(src));
}

// ---------------------------------------------------------------------------
// Weight pre-round: WR = tf32(W), elementwise (no transpose needed).
// grid (1024, 4), 256 threads, float4 per thread.
// ---------------------------------------------------------------------------
__global__ __launch_bounds__(256) void wround(
    const float* __restrict__ w0, const float* __restrict__ w1,
    const float* __restrict__ w2, const float* __restrict__ w3,
    float* __restrict__ dst)
{
    const int z = blockIdx.y;
    const float* src = (z == 0) ? w0 : (z == 1) ? w1 : (z == 2) ? w2 : w3;
    float* d = dst + (size_t)z * D_MODEL * D_MODEL;
    const size_t i4 = (size_t)blockIdx.x * 256 + threadIdx.x;   // float4 index
    float4 v = ((const float4*)src)[i4];
    ((float4*)d)[i4] = make_float4(f2tf(v.x), f2tf(v.y), f2tf(v.z), f2tf(v.w));
}

// ---------------------------------------------------------------------------
// tf32 mma.sync GEMM, 3-stage cp.async pipeline.
// C[Mx1024] = A[Mx1024] @ W[1024x1024] + bias.  Tile 128x128, BK=32.
// 8 warps (2m x 4n), warp tile 64x32, m16n8k8.
//   As stride 36 floats: a-frag bank = 4g+tg (bijective)
//   Bs stride 136 floats: b-frag bank = 8tg+g (bijective); rows are W[k][*]
// B staged via cp.async from pre-rounded WR; A via LDG+cvt+STS, 2 panels ahead.
// grid (8, 32, Z): z selects (A, W, bias, C) triple.
// ---------------------------------------------------------------------------
#define GBM 128
#define GBN 128
#define GBK 32
#define ASTRIDE 36
#define BSTRIDE 136
#define ST_A (GBM * ASTRIDE)            // 4608 floats
#define ST_B (GBK * BSTRIDE)            // 4352 floats
#define NSTAGE 3
#define GEMM_SMEM (NSTAGE * (ST_A + ST_B) * sizeof(float))   // 107520 B

__global__ __launch_bounds__(256, 2) void tgemm_pipe(
    const float* __restrict__ A0, const float* __restrict__ A1, const float* __restrict__ A2,
    const float* __restrict__ Wr,
    const float* __restrict__ b0, const float* __restrict__ b1, const float* __restrict__ b2,
    float* __restrict__ C0, float* __restrict__ C1, float* __restrict__ C2)
{
    extern __shared__ float sh[];
    const uint32_t sb = smem_u32(sh);

    const int z = blockIdx.z;
    const float* A    = (z == 0) ? A0 : (z == 1) ? A1 : A2;
    const float* W    = Wr + (size_t)z * D_MODEL * D_MODEL;   // caller offsets base
    const float* bias = (z == 0) ? b0 : (z == 1) ? b1 : b2;
    float* C          = (z == 0) ? C0 : (z == 1) ? C1 : C2;

    const int N = D_MODEL;
    const int tid  = threadIdx.x;
    const int bm   = blockIdx.y * GBM;
    const int bn   = blockIdx.x * GBN;
    const int warp = tid >> 5, lane = tid & 31;
    const int wm = warp & 1;
    const int wn = warp >> 1;
    const int g  = lane >> 2;
    const int tg = lane & 3;

    // A loader: idx = tid + i*256 -> m = idx>>3 (0..127... for i<4), kq = idx&7
    const int am0 = tid >> 3, akq = tid & 7;
    // B loader: 1024 16B-chunks: row = idx>>5 (0..31), c = idx&31
    const int br0 = tid >> 5, bc0 = tid & 31;

    float acc[4][4][4];
#pragma unroll
    for (int mi = 0; mi < 4; mi++)
#pragma unroll
        for (int nj = 0; nj < 4; nj++)
#pragma unroll
            for (int r = 0; r < 4; r++) acc[mi][nj][r] = 0.f;

    auto stage = [&](int p) {
        const int s = p % NSTAGE;
        float* As = sh + s * (ST_A + ST_B);
        const uint32_t Bs = sb + (uint32_t)(s * (ST_A + ST_B) + ST_A) * 4u;
        const int kp = p * GBK;
        // B: cp.async 4 chunks/thread from pre-rounded W[k][n]
#pragma unroll
        for (int i = 0; i < 4; i++) {
            const int idx = tid + i * 256;
            const int row = idx >> 5, c = idx & 31;
            cp16(Bs + (uint32_t)(row * BSTRIDE + c * 4) * 4u,
                 W + (size_t)(kp + row) * N + bn + c * 4);
        }
        asm volatile("cp.async.commit_group;" ::: "memory");
        // A: LDG -> tf32 -> STS, 4 float4/thread
#pragma unroll
        for (int i = 0; i < 4; i++) {
            const int idx = tid + i * 256;
            const int m = idx >> 3 & 127, kq = idx & 7;
            (void)idx;
            float4 v = *(const float4*)(A + (size_t)(bm + am0 + 32 * i) * D_MODEL + kp + akq * 4);
            *(float4*)&As[(am0 + 32 * i) * ASTRIDE + akq * 4] =
                make_float4(f2tf(v.x), f2tf(v.y), f2tf(v.z), f2tf(v.w));
            (void)m; (void)kq;
        }
    };

    stage(0);
    stage(1);

    const int NPAN = D_MODEL / GBK;   // 32
#pragma unroll 1
    for (int p = 0; p < NPAN; p++) {
        // stage p's B must have landed; allow stage p+1's group pending.
        if (p < NPAN - 2)
            asm volatile("cp.async.wait_group 1;" ::: "memory");
        else
            asm volatile("cp.async.wait_group 0;" ::: "memory");
        __syncthreads();

        if (p + 2 < NPAN) stage(p + 2);

        const int s = p % NSTAGE;
        const float* Ab = sh + s * (ST_A + ST_B);
        const float* Bb = Ab + ST_A;
#pragma unroll
        for (int ks = 0; ks < 4; ks++) {
            unsigned a[4][4], b[4][2];
#pragma unroll
            for (int mi = 0; mi < 4; mi++) {
                const int m0 = wm * 64 + mi * 16 + g;
                const int k0 = ks * 8 + tg;
                a[mi][0] = __float_as_uint(Ab[(m0)     * ASTRIDE + k0]);
                a[mi][1] = __float_as_uint(Ab[(m0 + 8) * ASTRIDE + k0]);
                a[mi][2] = __float_as_uint(Ab[(m0)     * ASTRIDE + k0 + 4]);
                a[mi][3] = __float_as_uint(Ab[(m0 + 8) * ASTRIDE + k0 + 4]);
            }
#pragma unroll
            for (int nj = 0; nj < 4; nj++) {
                const int n0 = wn * 32 + nj * 8 + g;
                const int k0 = ks * 8 + tg;
                b[nj][0] = __float_as_uint(Bb[(k0)     * BSTRIDE + n0]);
                b[nj][1] = __float_as_uint(Bb[(k0 + 4) * BSTRIDE + n0]);
            }
#pragma unroll
            for (int mi = 0; mi < 4; mi++)
#pragma unroll
                for (int nj = 0; nj < 4; nj++)
                    mma_tf32(acc[mi][nj], a[mi], b[nj]);
        }
        __syncthreads();
    }

    // Epilogue: bias + store
#pragma unroll
    for (int nj = 0; nj < 4; nj++) {
        const int col = bn + wn * 32 + nj * 8 + tg * 2;
        const float2 bv = *(const float2*)&bias[col];
#pragma unroll
        for (int mi = 0; mi < 4; mi++) {
            const int row0 = bm + wm * 64 + mi * 16 + g;
            float2 o0, o1;
            o0.x = acc[mi][nj][0] + bv.x;
            o0.y = acc[mi][nj][1] + bv.y;
            o1.x = acc[mi][nj][2] + bv.x;
            o1.y = acc[mi][nj][3] + bv.y;
            *(float2*)(C + (size_t)row0 * N + col)       = o0;
            *(float2*)(C + (size_t)(row0 + 8) * N + col) = o1;
        }
    }
}

// ---------------------------------------------------------------------------
// Tensor-core sparse local-window attention (unchanged from R5, 70.6us).
// ---------------------------------------------------------------------------
#define AKSTR 68
#define AVSTR 72
#define APSTR 68
#define AKS_F (256 * AKSTR)
#define AVS_F (256 * AVSTR)
#define APS_F (8 * 16 * APSTR)
#define ATTN_SMEM_B ((AKS_F + AVS_F + APS_F + 132) * sizeof(float))

__global__ __launch_bounds__(256) void attn_mma(
    const float* __restrict__ Q, const float* __restrict__ Kp,
    const float* __restrict__ Vp, const float* __restrict__ rel,
    float* __restrict__ O)
{
    extern __shared__ float sm[];
    float* Ks = sm;
    float* Vs = sm + AKS_F;
    float* Ps = sm + AKS_F + AVS_F;
    float* bs = sm + AKS_F + AVS_F + APS_F;

    const int t0   = blockIdx.x * 128;
    const int h    = blockIdx.y;
    const int b    = blockIdx.z;
    const int base = t0 - WIN;
    const int tid  = threadIdx.x;
    const int warp = tid >> 5, lane = tid & 31;
    const int g = lane >> 2, tg = lane & 3;

    const float* Kg = Kp + (size_t)b * T_SEQ * D_MODEL + h * DK;
    const float* Vg = Vp + (size_t)b * T_SEQ * D_MODEL + h * DK;

#pragma unroll
    for (int it = 0; it < 16; it++) {
        const int idx = tid + it * 256;
        const int key = idx >> 4, d4 = idx & 15;
        const int t   = base + key;
        float4 kv = make_float4(0.f, 0.f, 0.f, 0.f);
        float4 vv = make_float4(0.f, 0.f, 0.f, 0.f);
        if (t >= 0 && t < T_SEQ) {
            kv = *(const float4*)(Kg + (size_t)t * D_MODEL + d4 * 4);
            vv = *(const float4*)(Vg + (size_t)t * D_MODEL + d4 * 4);
        }
        *(float4*)&Ks[key * AKSTR + d4 * 4] =
            make_float4(f2tf(kv.x), f2tf(kv.y), f2tf(kv.z), f2tf(kv.w));
        *(float4*)&Vs[key * AVSTR + d4 * 4] =
            make_float4(f2tf(vv.x), f2tf(vv.y), f2tf(vv.z), f2tf(vv.w));
    }
    if (tid < 2 * WIN + 1)
        bs[tid] = rel[(size_t)(tid + MAXD - WIN) * H_HEADS + h];

    const int q0 = t0 + warp * 16;
    const float* Qg = Q + (size_t)(b * T_SEQ + q0) * D_MODEL + h * DK;
    unsigned qa[8][4];
#pragma unroll
    for (int kt = 0; kt < 8; kt++) {
        qa[kt][0] = __float_as_uint(f2tf(Qg[(size_t)g       * D_MODEL + kt * 8 + tg]));
        qa[kt][1] = __float_as_uint(f2tf(Qg[(size_t)(g + 8) * D_MODEL + kt * 8 + tg]));
        qa[kt][2] = __float_as_uint(f2tf(Qg[(size_t)g       * D_MODEL + kt * 8 + tg + 4]));
        qa[kt][3] = __float_as_uint(f2tf(Qg[(size_t)(g + 8) * D_MODEL + kt * 8 + tg + 4]));
    }
    __syncthreads();

    float oacc[8][4];
#pragma unroll
    for (int nt = 0; nt < 8; nt++)
#pragma unroll
        for (int r = 0; r < 4; r++) oacc[nt][r] = 0.f;
    float rs0 = 0.f, rs1 = 0.f;
    float* Pw = Ps + warp * 16 * APSTR;

#pragma unroll 1
    for (int c = 0; c < 4; c++) {
        float sacc[8][4];
#pragma unroll
        for (int nt = 0; nt < 8; nt++)
#pragma unroll
            for (int r = 0; r < 4; r++) sacc[nt][r] = 0.f;
#pragma unroll
        for (int nt = 0; nt < 8; nt++) {
            const float* kb = Ks + (size_t)(c * 64 + nt * 8 + g) * AKSTR + tg;
#pragma unroll
            for (int kt = 0; kt < 8; kt++) {
                unsigned bf[2];
                bf[0] = __float_as_uint(kb[kt * 8]);
                bf[1] = __float_as_uint(kb[kt * 8 + 4]);
                mma_tf32(sacc[nt], qa[kt], bf);
            }
        }

        __syncwarp();
#pragma unroll
        for (int nt = 0; nt < 8; nt++) {
            const int col = c * 64 + nt * 8 + 2 * tg;
            const int tk  = base + col;
            const int d0  = tk - (q0 + g);
            const int d2  = tk - (q0 + 8 + g);
            float e0 = 0.f, e1 = 0.f, e2 = 0.f, e3 = 0.f;
            if (tk >= 0 && tk < T_SEQ) {
                if (d0 >= -WIN && d0 <= WIN) e0 = __expf(sacc[nt][0] * 0.125f + bs[d0 + WIN]);
                if (d2 >= -WIN && d2 <= WIN) e2 = __expf(sacc[nt][2] * 0.125f + bs[d2 + WIN]);
            }
            if (tk + 1 >= 0 && tk + 1 < T_SEQ) {
                if (d0 + 1 >= -WIN && d0 + 1 <= WIN) e1 = __expf(sacc[nt][1] * 0.125f + bs[d0 + 1 + WIN]);
                if (d2 + 1 >= -WIN && d2 + 1 <= WIN) e3 = __expf(sacc[nt][3] * 0.125f + bs[d2 + 1 + WIN]);
            }
            rs0 += e0 + e1;
            rs1 += e2 + e3;
            *(float2*)&Pw[(size_t)g       * APSTR + nt * 8 + 2 * tg] = make_float2(f2tf(e0), f2tf(e1));
            *(float2*)&Pw[(size_t)(g + 8) * APSTR + nt * 8 + 2 * tg] = make_float2(f2tf(e2), f2tf(e3));
        }
        __syncwarp();

#pragma unroll
        for (int kt = 0; kt < 8; kt++) {
            unsigned pa[4];
            pa[0] = __float_as_uint(Pw[(size_t)g       * APSTR + kt * 8 + tg]);
            pa[1] = __float_as_uint(Pw[(size_t)(g + 8) * APSTR + kt * 8 + tg]);
            pa[2] = __float_as_uint(Pw[(size_t)g       * APSTR + kt * 8 + tg + 4]);
            pa[3] = __float_as_uint(Pw[(size_t)(g + 8) * APSTR + kt * 8 + tg + 4]);
            const float* vb = Vs + (size_t)(c * 64 + kt * 8 + tg) * AVSTR + g;
#pragma unroll
            for (int nt = 0; nt < 8; nt++) {
                unsigned bf[2];
                bf[0] = __float_as_uint(vb[nt * 8]);
                bf[1] = __float_as_uint(vb[4 * AVSTR + nt * 8]);
                mma_tf32(oacc[nt], pa, bf);
            }
        }
    }

    rs0 += __shfl_xor_sync(0xffffffffu, rs0, 1);
    rs0 += __shfl_xor_sync(0xffffffffu, rs0, 2);
    rs1 += __shfl_xor_sync(0xffffffffu, rs1, 1);
    rs1 += __shfl_xor_sync(0xffffffffu, rs1, 2);
    const float i0 = 1.f / rs0, i1 = 1.f / rs1;

    float* Og = O + (size_t)(b * T_SEQ + q0) * D_MODEL + h * DK;
#pragma unroll
    for (int nt = 0; nt < 8; nt++) {
        *(float2*)&Og[(size_t)g       * D_MODEL + nt * 8 + 2 * tg] =
            make_float2(oacc[nt][0] * i0, oacc[nt][1] * i0);
        *(float2*)&Og[(size_t)(g + 8) * D_MODEL + nt * 8 + 2 * tg] =
            make_float2(oacc[nt][2] * i1, oacc[nt][3] * i1);
    }
}

// ---------------------------------------------------------------------------
// Launch
// ---------------------------------------------------------------------------
extern "C" void kernel_launch(void* const* d_in, const int* in_sizes, int n_in,
                              void* d_out, int out_size)
{
    const float* q_in = (const float*)d_in[0];
    const float* k_in = (const float*)d_in[1];
    const float* v_in = (const float*)d_in[2];
    const float* Wq   = (const float*)d_in[3];
    const float* bq   = (const float*)d_in[4];
    const float* Wk   = (const float*)d_in[5];
    const float* bk   = (const float*)d_in[6];
    const float* Wv   = (const float*)d_in[7];
    const float* bv   = (const float*)d_in[8];
    const float* Wo   = (const float*)d_in[9];
    const float* bo   = (const float*)d_in[10];
    const float* rel  = (const float*)d_in[11];
    float* out = (float*)d_out;

    float *pQ, *pK, *pV, *pA, *pWR;
    cudaGetSymbolAddress((void**)&pQ, g_Q);
    cudaGetSymbolAddress((void**)&pK, g_K);
    cudaGetSymbolAddress((void**)&pV, g_V);
    cudaGetSymbolAddress((void**)&pA, g_A);
    cudaGetSymbolAddress((void**)&pWR, g_WR);

    cudaFuncSetAttribute(tgemm_pipe, cudaFuncAttributeMaxDynamicSharedMemorySize,
                         (int)GEMM_SMEM);
    cudaFuncSetAttribute(attn_mma, cudaFuncAttributeMaxDynamicSharedMemorySize,
                         (int)ATTN_SMEM_B);

    const size_t WSZ = (size_t)D_MODEL * D_MODEL;

    // Pre-round all 4 weight matrices to tf32 (enables cp.async B staging).
    wround<<<dim3(D_MODEL * D_MODEL / 4 / 256, 4), 256>>>(Wq, Wk, Wv, Wo, pWR);

    // Fused Q/K/V projections: one launch, grid.z selects the triple.
    dim3 g3(D_MODEL / GBN, M_ROWS / GBM, 3);
    tgemm_pipe<<<g3, 256, GEMM_SMEM>>>(q_in, k_in, v_in, pWR,
                                       bq, bk, bv, pQ, pK, pV);

    attn_mma<<<dim3(T_SEQ / 128, H_HEADS, B_SZ), 256, ATTN_SMEM_B>>>(pQ, pK, pV, rel, pA);

    // Output projection (z=0 path, weight base offset 3*WSZ).
    dim3 g1(D_MODEL / GBN, M_ROWS / GBM, 1);
    tgemm_pipe<<<g1, 256, GEMM_SMEM>>>(pA, pA, pA, pWR + 3 * WSZ,
                                       bo, bo, bo, out, out, out);
}

// round 8
// speedup vs baseline: 3.9920x; 1.3920x over previous
#include <cuda_runtime.h>
#include <cuda_fp16.h>
#include <cstdint>

// Problem constants
#define B_SZ    2
#define T_SEQ   2048
#define D_MODEL 1024
#define H_HEADS 16
#define DK      64
#define M_ROWS  (B_SZ * T_SEQ)   // 4096
#define WIN     64
#define MAXD    128

// ---------------------------------------------------------------------------
// Scratch
// ---------------------------------------------------------------------------
__device__ float  g_Q[(size_t)M_ROWS * D_MODEL];
__device__ float  g_K[(size_t)M_ROWS * D_MODEL];
__device__ float  g_V[(size_t)M_ROWS * D_MODEL];
__device__ float  g_A[(size_t)M_ROWS * D_MODEL];
__device__ __half g_WT[(size_t)4 * D_MODEL * D_MODEL];  // transposed fp16 weights [z][n][k]

__device__ __forceinline__ float f2tf(float x) {
    unsigned r;
    asm("cvt.rna.tf32.f32 %0, %1;" : "=r"(r) : "f"(x));
    return __uint_as_float(r);
}

__device__ __forceinline__ void mma_tf32(float* c, const unsigned* a, const unsigned* b) {
    asm volatile(
        "mma.sync.aligned.m16n8k8.row.col.f32.tf32.tf32.f32 "
        "{%0,%1,%2,%3}, {%4,%5,%6,%7}, {%8,%9}, {%0,%1,%2,%3};\n"
        : "+f"(c[0]), "+f"(c[1]), "+f"(c[2]), "+f"(c[3])
        : "r"(a[0]), "r"(a[1]), "r"(a[2]), "r"(a[3]), "r"(b[0]), "r"(b[1]));
}

__device__ __forceinline__ void mma_f16(float* c, const unsigned* a, const unsigned* b) {
    asm volatile(
        "mma.sync.aligned.m16n8k16.row.col.f32.f16.f16.f32 "
        "{%0,%1,%2,%3}, {%4,%5,%6,%7}, {%8,%9}, {%0,%1,%2,%3};\n"
        : "+f"(c[0]), "+f"(c[1]), "+f"(c[2]), "+f"(c[3])
        : "r"(a[0]), "r"(a[1]), "r"(a[2]), "r"(a[3]), "r"(b[0]), "r"(b[1]));
}

__device__ __forceinline__ uint32_t smem_u32(const void* p) {
    uint32_t a;
    asm("{ .reg .u64 t; cvta.to.shared.u64 t, %1; cvt.u32.u64 %0, t; }" : "=r"(a) : "l"(p));
    return a;
}

__device__ __forceinline__ void cp16(uint32_t dst, const void* src) {
    asm volatile("cp.async.cg.shared.global [%0], [%1], 16;" :: "r"(dst), "l"(src));
}

// ---------------------------------------------------------------------------
// Weight transpose + fp16 convert: WT[z][n][k] = half(W[k][n]). grid (32,32,4)
// ---------------------------------------------------------------------------
__global__ __launch_bounds__(256) void wtrans_h(
    const float* __restrict__ w0, const float* __restrict__ w1,
    const float* __restrict__ w2, const float* __restrict__ w3,
    __half* __restrict__ dst)
{
    __shared__ float t[32][33];
    const int z = blockIdx.z;
    const float* src = (z == 0) ? w0 : (z == 1) ? w1 : (z == 2) ? w2 : w3;
    __half* d = dst + (size_t)z * D_MODEL * D_MODEL;
    const int tx = threadIdx.x, ty = threadIdx.y;
    const int x = blockIdx.x * 32 + tx;   // n
    const int y = blockIdx.y * 32 + ty;   // k
#pragma unroll
    for (int j = 0; j < 32; j += 8)
        t[ty + j][tx] = src[(size_t)(y + j) * D_MODEL + x];
    __syncthreads();
    const int xo = blockIdx.y * 32 + tx;  // k
    const int yo = blockIdx.x * 32 + ty;  // n
#pragma unroll
    for (int j = 0; j < 32; j += 8)
        d[(size_t)(yo + j) * D_MODEL + xo] = __float2half(t[tx][ty + j]);
}

// ---------------------------------------------------------------------------
// fp16 mma.sync GEMM, 3-stage cp.async (B) + register-prefetch (A).
// C[Mx1024] = A[Mx1024] @ W + bias,  W given as WT[n][k] fp16.
// Tile 128x128, BK=32, 8 warps (2m x 4n), m16n8k16, 2 k-steps/panel.
// SMEM halves, stride 40: fragment LDS bank = (20g+tg) mod 32, bijective.
// grid (8, 32, Z).
// ---------------------------------------------------------------------------
#define GBM 128
#define GBN 128
#define GBK 32
#define HSTR 40                         // halves
#define HST_A (GBM * HSTR)              // 5120 halves
#define HST_B (GBN * HSTR)              // 5120 halves
#define NSTAGE 3
#define GEMM_SMEM (NSTAGE * (HST_A + HST_B) * 2)   // 61440 B

__global__ __launch_bounds__(256, 2) void hgemm_pipe(
    const float* __restrict__ A0, const float* __restrict__ A1, const float* __restrict__ A2,
    const __half* __restrict__ Wt,
    const float* __restrict__ b0, const float* __restrict__ b1, const float* __restrict__ b2,
    float* __restrict__ C0, float* __restrict__ C1, float* __restrict__ C2)
{
    extern __shared__ __half shh[];
    const uint32_t sb = smem_u32(shh);

    const int z = blockIdx.z;
    const float* A    = (z == 0) ? A0 : (z == 1) ? A1 : A2;
    const __half* W   = Wt + (size_t)z * D_MODEL * D_MODEL;
    const float* bias = (z == 0) ? b0 : (z == 1) ? b1 : b2;
    float* C          = (z == 0) ? C0 : (z == 1) ? C1 : C2;

    const int N = D_MODEL;
    const int tid  = threadIdx.x;
    const int bm   = blockIdx.y * GBM;
    const int bn   = blockIdx.x * GBN;
    const int warp = tid >> 5, lane = tid & 31;
    const int wm = warp & 1;
    const int wn = warp >> 1;
    const int g  = lane >> 2;
    const int tg = lane & 3;

    const int am0 = tid >> 3, akq = tid & 7;   // A loader: m = am0+32i, 4 floats at akq*4

    float acc[4][4][4];
#pragma unroll
    for (int mi = 0; mi < 4; mi++)
#pragma unroll
        for (int nj = 0; nj < 4; nj++)
#pragma unroll
            for (int r = 0; r < 4; r++) acc[mi][nj][r] = 0.f;

    auto stageB = [&](int p) {
        const int s = p % NSTAGE;
        const uint32_t Bsb = sb + (uint32_t)(s * (HST_A + HST_B) + HST_A) * 2u;
        const int kp = p * GBK;
#pragma unroll
        for (int i = 0; i < 2; i++) {     // 512 16B chunks over 256 threads
            const int idx = tid + i * 256;
            const int n = idx >> 2, c = idx & 3;
            cp16(Bsb + (uint32_t)(n * (HSTR * 2) + c * 16),
                 W + (size_t)(bn + n) * N + kp + c * 8);
        }
        asm volatile("cp.async.commit_group;" ::: "memory");
    };
    auto ldA = [&](int p, float4* ar) {
        const int kp = p * GBK;
#pragma unroll
        for (int i = 0; i < 4; i++)
            ar[i] = *(const float4*)(A + (size_t)(bm + am0 + 32 * i) * D_MODEL + kp + akq * 4);
    };
    auto stA = [&](int p, const float4* ar) {
        const int s = p % NSTAGE;
        __half* As = shh + s * (HST_A + HST_B);
#pragma unroll
        for (int i = 0; i < 4; i++) {
            __half2 h0 = __floats2half2_rn(ar[i].x, ar[i].y);
            __half2 h1 = __floats2half2_rn(ar[i].z, ar[i].w);
            *(__half2*)&As[(am0 + 32 * i) * HSTR + akq * 4]     = h0;
            *(__half2*)&As[(am0 + 32 * i) * HSTR + akq * 4 + 2] = h1;
        }
    };

    // Preamble: B(0), B(1) in flight; A(0), A(1) staged synchronously.
    stageB(0);
    stageB(1);
    {
        float4 t[4];
        ldA(0, t); stA(0, t);
        ldA(1, t); stA(1, t);
    }

    const int NPAN = D_MODEL / GBK;   // 32
#pragma unroll 1
    for (int p = 0; p < NPAN; p++) {
        if (p < NPAN - 1)
            asm volatile("cp.async.wait_group 1;" ::: "memory");
        else
            asm volatile("cp.async.wait_group 0;" ::: "memory");
        __syncthreads();

        float4 ar[4];
        const bool pre = (p + 2 < NPAN);
        if (pre) {
            ldA(p + 2, ar);       // LDG in flight across the MMA section
            stageB(p + 2);
        }

        const int s = p % NSTAGE;
        const __half* Ab = shh + s * (HST_A + HST_B);
        const __half* Bb = Ab + HST_A;
#pragma unroll
        for (int ks = 0; ks < 2; ks++) {
            unsigned a[4][4], b[4][2];
#pragma unroll
            for (int mi = 0; mi < 4; mi++) {
                const __half* ap = Ab + (wm * 64 + mi * 16 + g) * HSTR + ks * 16 + 2 * tg;
                a[mi][0] = *(const unsigned*)(ap);
                a[mi][1] = *(const unsigned*)(ap + 8 * HSTR);
                a[mi][2] = *(const unsigned*)(ap + 8);
                a[mi][3] = *(const unsigned*)(ap + 8 * HSTR + 8);
            }
#pragma unroll
            for (int nj = 0; nj < 4; nj++) {
                const __half* bp = Bb + (wn * 32 + nj * 8 + g) * HSTR + ks * 16 + 2 * tg;
                b[nj][0] = *(const unsigned*)(bp);
                b[nj][1] = *(const unsigned*)(bp + 8);
            }
#pragma unroll
            for (int mi = 0; mi < 4; mi++)
#pragma unroll
                for (int nj = 0; nj < 4; nj++)
                    mma_f16(acc[mi][nj], a[mi], b[nj]);
        }

        if (pre) stA(p + 2, ar);   // STS after MMAs; next iter's sync orders it
    }

    // Epilogue: bias + store (C layout of m16n8 is same as tf32 path)
#pragma unroll
    for (int nj = 0; nj < 4; nj++) {
        const int col = bn + wn * 32 + nj * 8 + tg * 2;
        const float2 bv = *(const float2*)&bias[col];
#pragma unroll
        for (int mi = 0; mi < 4; mi++) {
            const int row0 = bm + wm * 64 + mi * 16 + g;
            float2 o0, o1;
            o0.x = acc[mi][nj][0] + bv.x;
            o0.y = acc[mi][nj][1] + bv.y;
            o1.x = acc[mi][nj][2] + bv.x;
            o1.y = acc[mi][nj][3] + bv.y;
            *(float2*)(C + (size_t)row0 * N + col)       = o0;
            *(float2*)(C + (size_t)(row0 + 8) * N + col) = o1;
        }
    }
}

// ---------------------------------------------------------------------------
// Tensor-core sparse local-window attention (unchanged from R5, 70.6us).
// ---------------------------------------------------------------------------
#define AKSTR 68
#define AVSTR 72
#define APSTR 68
#define AKS_F (256 * AKSTR)
#define AVS_F (256 * AVSTR)
#define APS_F (8 * 16 * APSTR)
#define ATTN_SMEM_B ((AKS_F + AVS_F + APS_F + 132) * sizeof(float))

__global__ __launch_bounds__(256) void attn_mma(
    const float* __restrict__ Q, const float* __restrict__ Kp,
    const float* __restrict__ Vp, const float* __restrict__ rel,
    float* __restrict__ O)
{
    extern __shared__ float sm[];
    float* Ks = sm;
    float* Vs = sm + AKS_F;
    float* Ps = sm + AKS_F + AVS_F;
    float* bs = sm + AKS_F + AVS_F + APS_F;

    const int t0   = blockIdx.x * 128;
    const int h    = blockIdx.y;
    const int b    = blockIdx.z;
    const int base = t0 - WIN;
    const int tid  = threadIdx.x;
    const int warp = tid >> 5, lane = tid & 31;
    const int g = lane >> 2, tg = lane & 3;

    const float* Kg = Kp + (size_t)b * T_SEQ * D_MODEL + h * DK;
    const float* Vg = Vp + (size_t)b * T_SEQ * D_MODEL + h * DK;

#pragma unroll
    for (int it = 0; it < 16; it++) {
        const int idx = tid + it * 256;
        const int key = idx >> 4, d4 = idx & 15;
        const int t   = base + key;
        float4 kv = make_float4(0.f, 0.f, 0.f, 0.f);
        float4 vv = make_float4(0.f, 0.f, 0.f, 0.f);
        if (t >= 0 && t < T_SEQ) {
            kv = *(const float4*)(Kg + (size_t)t * D_MODEL + d4 * 4);
            vv = *(const float4*)(Vg + (size_t)t * D_MODEL + d4 * 4);
        }
        *(float4*)&Ks[key * AKSTR + d4 * 4] =
            make_float4(f2tf(kv.x), f2tf(kv.y), f2tf(kv.z), f2tf(kv.w));
        *(float4*)&Vs[key * AVSTR + d4 * 4] =
            make_float4(f2tf(vv.x), f2tf(vv.y), f2tf(vv.z), f2tf(vv.w));
    }
    if (tid < 2 * WIN + 1)
        bs[tid] = rel[(size_t)(tid + MAXD - WIN) * H_HEADS + h];

    const int q0 = t0 + warp * 16;
    const float* Qg = Q + (size_t)(b * T_SEQ + q0) * D_MODEL + h * DK;
    unsigned qa[8][4];
#pragma unroll
    for (int kt = 0; kt < 8; kt++) {
        qa[kt][0] = __float_as_uint(f2tf(Qg[(size_t)g       * D_MODEL + kt * 8 + tg]));
        qa[kt][1] = __float_as_uint(f2tf(Qg[(size_t)(g + 8) * D_MODEL + kt * 8 + tg]));
        qa[kt][2] = __float_as_uint(f2tf(Qg[(size_t)g       * D_MODEL + kt * 8 + tg + 4]));
        qa[kt][3] = __float_as_uint(f2tf(Qg[(size_t)(g + 8) * D_MODEL + kt * 8 + tg + 4]));
    }
    __syncthreads();

    float oacc[8][4];
#pragma unroll
    for (int nt = 0; nt < 8; nt++)
#pragma unroll
        for (int r = 0; r < 4; r++) oacc[nt][r] = 0.f;
    float rs0 = 0.f, rs1 = 0.f;
    float* Pw = Ps + warp * 16 * APSTR;

#pragma unroll 1
    for (int c = 0; c < 4; c++) {
        float sacc[8][4];
#pragma unroll
        for (int nt = 0; nt < 8; nt++)
#pragma unroll
            for (int r = 0; r < 4; r++) sacc[nt][r] = 0.f;
#pragma unroll
        for (int nt = 0; nt < 8; nt++) {
            const float* kb = Ks + (size_t)(c * 64 + nt * 8 + g) * AKSTR + tg;
#pragma unroll
            for (int kt = 0; kt < 8; kt++) {
                unsigned bf[2];
                bf[0] = __float_as_uint(kb[kt * 8]);
                bf[1] = __float_as_uint(kb[kt * 8 + 4]);
                mma_tf32(sacc[nt], qa[kt], bf);
            }
        }

        __syncwarp();
#pragma unroll
        for (int nt = 0; nt < 8; nt++) {
            const int col = c * 64 + nt * 8 + 2 * tg;
            const int tk  = base + col;
            const int d0  = tk - (q0 + g);
            const int d2  = tk - (q0 + 8 + g);
            float e0 = 0.f, e1 = 0.f, e2 = 0.f, e3 = 0.f;
            if (tk >= 0 && tk < T_SEQ) {
                if (d0 >= -WIN && d0 <= WIN) e0 = __expf(sacc[nt][0] * 0.125f + bs[d0 + WIN]);
                if (d2 >= -WIN && d2 <= WIN) e2 = __expf(sacc[nt][2] * 0.125f + bs[d2 + WIN]);
            }
            if (tk + 1 >= 0 && tk + 1 < T_SEQ) {
                if (d0 + 1 >= -WIN && d0 + 1 <= WIN) e1 = __expf(sacc[nt][1] * 0.125f + bs[d0 + 1 + WIN]);
                if (d2 + 1 >= -WIN && d2 + 1 <= WIN) e3 = __expf(sacc[nt][3] * 0.125f + bs[d2 + 1 + WIN]);
            }
            rs0 += e0 + e1;
            rs1 += e2 + e3;
            *(float2*)&Pw[(size_t)g       * APSTR + nt * 8 + 2 * tg] = make_float2(f2tf(e0), f2tf(e1));
            *(float2*)&Pw[(size_t)(g + 8) * APSTR + nt * 8 + 2 * tg] = make_float2(f2tf(e2), f2tf(e3));
        }
        __syncwarp();

#pragma unroll
        for (int kt = 0; kt < 8; kt++) {
            unsigned pa[4];
            pa[0] = __float_as_uint(Pw[(size_t)g       * APSTR + kt * 8 + tg]);
            pa[1] = __float_as_uint(Pw[(size_t)(g + 8) * APSTR + kt * 8 + tg]);
            pa[2] = __float_as_uint(Pw[(size_t)g       * APSTR + kt * 8 + tg + 4]);
            pa[3] = __float_as_uint(Pw[(size_t)(g + 8) * APSTR + kt * 8 + tg + 4]);
            const float* vb = Vs + (size_t)(c * 64 + kt * 8 + tg) * AVSTR + g;
#pragma unroll
            for (int nt = 0; nt < 8; nt++) {
                unsigned bf[2];
                bf[0] = __float_as_uint(vb[nt * 8]);
                bf[1] = __float_as_uint(vb[4 * AVSTR + nt * 8]);
                mma_tf32(oacc[nt], pa, bf);
            }
        }
    }

    rs0 += __shfl_xor_sync(0xffffffffu, rs0, 1);
    rs0 += __shfl_xor_sync(0xffffffffu, rs0, 2);
    rs1 += __shfl_xor_sync(0xffffffffu, rs1, 1);
    rs1 += __shfl_xor_sync(0xffffffffu, rs1, 2);
    const float i0 = 1.f / rs0, i1 = 1.f / rs1;

    float* Og = O + (size_t)(b * T_SEQ + q0) * D_MODEL + h * DK;
#pragma unroll
    for (int nt = 0; nt < 8; nt++) {
        *(float2*)&Og[(size_t)g       * D_MODEL + nt * 8 + 2 * tg] =
            make_float2(oacc[nt][0] * i0, oacc[nt][1] * i0);
        *(float2*)&Og[(size_t)(g + 8) * D_MODEL + nt * 8 + 2 * tg] =
            make_float2(oacc[nt][2] * i1, oacc[nt][3] * i1);
    }
}

// ---------------------------------------------------------------------------
// Launch
// ---------------------------------------------------------------------------
extern "C" void kernel_launch(void* const* d_in, const int* in_sizes, int n_in,
                              void* d_out, int out_size)
{
    const float* q_in = (const float*)d_in[0];
    const float* k_in = (const float*)d_in[1];
    const float* v_in = (const float*)d_in[2];
    const float* Wq   = (const float*)d_in[3];
    const float* bq   = (const float*)d_in[4];
    const float* Wk   = (const float*)d_in[5];
    const float* bk   = (const float*)d_in[6];
    const float* Wv   = (const float*)d_in[7];
    const float* bv   = (const float*)d_in[8];
    const float* Wo   = (const float*)d_in[9];
    const float* bo   = (const float*)d_in[10];
    const float* rel  = (const float*)d_in[11];
    float* out = (float*)d_out;

    float *pQ, *pK, *pV, *pA;
    __half* pWT;
    cudaGetSymbolAddress((void**)&pQ, g_Q);
    cudaGetSymbolAddress((void**)&pK, g_K);
    cudaGetSymbolAddress((void**)&pV, g_V);
    cudaGetSymbolAddress((void**)&pA, g_A);
    cudaGetSymbolAddress((void**)&pWT, g_WT);

    cudaFuncSetAttribute(hgemm_pipe, cudaFuncAttributeMaxDynamicSharedMemorySize,
                         (int)GEMM_SMEM);
    cudaFuncSetAttribute(attn_mma, cudaFuncAttributeMaxDynamicSharedMemorySize,
                         (int)ATTN_SMEM_B);

    const size_t WSZ = (size_t)D_MODEL * D_MODEL;

    // Transpose + fp16-convert all 4 weights.
    wtrans_h<<<dim3(32, 32, 4), dim3(32, 8)>>>(Wq, Wk, Wv, Wo, pWT);

    // Fused Q/K/V projections.
    dim3 g3(D_MODEL / GBN, M_ROWS / GBM, 3);
    hgemm_pipe<<<g3, 256, GEMM_SMEM>>>(q_in, k_in, v_in, pWT,
                                       bq, bk, bv, pQ, pK, pV);

    attn_mma<<<dim3(T_SEQ / 128, H_HEADS, B_SZ), 256, ATTN_SMEM_B>>>(pQ, pK, pV, rel, pA);

    // Output projection.
    dim3 g1(D_MODEL / GBN, M_ROWS / GBM, 1);
    hgemm_pipe<<<g1, 256, GEMM_SMEM>>>(pA, pA, pA, pWT + 3 * WSZ,
                                       bo, bo, bo, out, out, out);
}

// round 9
// speedup vs baseline: 4.8428x; 1.2131x over previous
#include <cuda_runtime.h>
#include <cuda_fp16.h>
#include <cstdint>

// Problem constants
#define B_SZ    2
#define T_SEQ   2048
#define D_MODEL 1024
#define H_HEADS 16
#define DK      64
#define M_ROWS  (B_SZ * T_SEQ)   // 4096
#define WIN     64
#define MAXD    128

// ---------------------------------------------------------------------------
// Scratch
// ---------------------------------------------------------------------------
__device__ float  g_Q[(size_t)M_ROWS * D_MODEL];
__device__ float  g_K[(size_t)M_ROWS * D_MODEL];
__device__ float  g_V[(size_t)M_ROWS * D_MODEL];
__device__ float  g_A[(size_t)M_ROWS * D_MODEL];
__device__ __half g_WT[(size_t)4 * D_MODEL * D_MODEL];  // transposed fp16 weights [z][n][k]

__device__ __forceinline__ void mma_f16(float* c, const unsigned* a, const unsigned* b) {
    asm volatile(
        "mma.sync.aligned.m16n8k16.row.col.f32.f16.f16.f32 "
        "{%0,%1,%2,%3}, {%4,%5,%6,%7}, {%8,%9}, {%0,%1,%2,%3};\n"
        : "+f"(c[0]), "+f"(c[1]), "+f"(c[2]), "+f"(c[3])
        : "r"(a[0]), "r"(a[1]), "r"(a[2]), "r"(a[3]), "r"(b[0]), "r"(b[1]));
}

#define LDSM4(R0, R1, R2, R3, ADDR)                                           \
    asm volatile("ldmatrix.sync.aligned.m8n8.x4.shared.b16 {%0,%1,%2,%3}, [%4];" \
                 : "=r"(R0), "=r"(R1), "=r"(R2), "=r"(R3) : "r"(ADDR))
#define LDSM4T(R0, R1, R2, R3, ADDR)                                          \
    asm volatile("ldmatrix.sync.aligned.m8n8.x4.trans.shared.b16 {%0,%1,%2,%3}, [%4];" \
                 : "=r"(R0), "=r"(R1), "=r"(R2), "=r"(R3) : "r"(ADDR))

__device__ __forceinline__ uint32_t smem_u32(const void* p) {
    uint32_t a;
    asm("{ .reg .u64 t; cvta.to.shared.u64 t, %1; cvt.u32.u64 %0, t; }" : "=r"(a) : "l"(p));
    return a;
}

__device__ __forceinline__ void cp16(uint32_t dst, const void* src) {
    asm volatile("cp.async.cg.shared.global [%0], [%1], 16;" :: "r"(dst), "l"(src));
}

__device__ __forceinline__ unsigned h2u(__half2 h) {
    return *(unsigned*)&h;
}

// ---------------------------------------------------------------------------
// Weight transpose + fp16 convert: WT[z][n][k] = half(W[k][n]). grid (32,32,4)
// ---------------------------------------------------------------------------
__global__ __launch_bounds__(256) void wtrans_h(
    const float* __restrict__ w0, const float* __restrict__ w1,
    const float* __restrict__ w2, const float* __restrict__ w3,
    __half* __restrict__ dst)
{
    __shared__ float t[32][33];
    const int z = blockIdx.z;
    const float* src = (z == 0) ? w0 : (z == 1) ? w1 : (z == 2) ? w2 : w3;
    __half* d = dst + (size_t)z * D_MODEL * D_MODEL;
    const int tx = threadIdx.x, ty = threadIdx.y;
    const int x = blockIdx.x * 32 + tx;
    const int y = blockIdx.y * 32 + ty;
#pragma unroll
    for (int j = 0; j < 32; j += 8)
        t[ty + j][tx] = src[(size_t)(y + j) * D_MODEL + x];
    __syncthreads();
    const int xo = blockIdx.y * 32 + tx;
    const int yo = blockIdx.x * 32 + ty;
#pragma unroll
    for (int j = 0; j < 32; j += 8)
        d[(size_t)(yo + j) * D_MODEL + xo] = __float2half(t[tx][ty + j]);
}

// ---------------------------------------------------------------------------
// fp16 mma.sync GEMM with ldmatrix fragments.
// Tile 128x128, BK=32, 8 warps (2m x 4n), m16n8k16.
// SMEM halves stride 40 (80B rows = 5x16B): ldmatrix conflict-free.
// ---------------------------------------------------------------------------
#define GBM 128
#define GBN 128
#define GBK 32
#define HSTR 40
#define HST_A (GBM * HSTR)
#define HST_B (GBN * HSTR)
#define NSTAGE 3
#define GEMM_SMEM (NSTAGE * (HST_A + HST_B) * 2)   // 61440 B

__global__ __launch_bounds__(256, 2) void hgemm_pipe(
    const float* __restrict__ A0, const float* __restrict__ A1, const float* __restrict__ A2,
    const __half* __restrict__ Wt,
    const float* __restrict__ b0, const float* __restrict__ b1, const float* __restrict__ b2,
    float* __restrict__ C0, float* __restrict__ C1, float* __restrict__ C2)
{
    extern __shared__ __half shh[];
    const uint32_t sb = smem_u32(shh);

    const int z = blockIdx.z;
    const float* A    = (z == 0) ? A0 : (z == 1) ? A1 : A2;
    const __half* W   = Wt + (size_t)z * D_MODEL * D_MODEL;
    const float* bias = (z == 0) ? b0 : (z == 1) ? b1 : b2;
    float* C          = (z == 0) ? C0 : (z == 1) ? C1 : C2;

    const int N = D_MODEL;
    const int tid  = threadIdx.x;
    const int bm   = blockIdx.y * GBM;
    const int bn   = blockIdx.x * GBN;
    const int warp = tid >> 5, lane = tid & 31;
    const int wm = warp & 1;
    const int wn = warp >> 1;
    const int g  = lane >> 2;
    const int tg = lane & 3;
    const int lj = lane >> 3, lr = lane & 7;

    const int am0 = tid >> 3, akq = tid & 7;

    // Per-lane invariant fragment address pieces (halves)
    const uint32_t a_base = (uint32_t)((wm * 64 + (lj & 1) * 8 + lr) * HSTR + (lj >> 1) * 8);
    const uint32_t b_base = (uint32_t)((wn * 32 + (lj >> 1) * 8 + lr) * HSTR + (lj & 1) * 8);

    float acc[4][4][4];
#pragma unroll
    for (int mi = 0; mi < 4; mi++)
#pragma unroll
        for (int nj = 0; nj < 4; nj++)
#pragma unroll
            for (int r = 0; r < 4; r++) acc[mi][nj][r] = 0.f;

    auto stageB = [&](int p) {
        const int s = p % NSTAGE;
        const uint32_t Bsb = sb + (uint32_t)(s * (HST_A + HST_B) + HST_A) * 2u;
        const int kp = p * GBK;
#pragma unroll
        for (int i = 0; i < 2; i++) {
            const int idx = tid + i * 256;
            const int n = idx >> 2, c = idx & 3;
            cp16(Bsb + (uint32_t)(n * (HSTR * 2) + c * 16),
                 W + (size_t)(bn + n) * N + kp + c * 8);
        }
        asm volatile("cp.async.commit_group;" ::: "memory");
    };
    auto ldA = [&](int p, float4* ar) {
        const int kp = p * GBK;
#pragma unroll
        for (int i = 0; i < 4; i++)
            ar[i] = *(const float4*)(A + (size_t)(bm + am0 + 32 * i) * D_MODEL + kp + akq * 4);
    };
    auto stA = [&](int p, const float4* ar) {
        const int s = p % NSTAGE;
        __half* As = shh + s * (HST_A + HST_B);
#pragma unroll
        for (int i = 0; i < 4; i++) {
            __half2 h0 = __floats2half2_rn(ar[i].x, ar[i].y);
            __half2 h1 = __floats2half2_rn(ar[i].z, ar[i].w);
            *(__half2*)&As[(am0 + 32 * i) * HSTR + akq * 4]     = h0;
            *(__half2*)&As[(am0 + 32 * i) * HSTR + akq * 4 + 2] = h1;
        }
    };

    stageB(0);
    stageB(1);
    {
        float4 t[4];
        ldA(0, t); stA(0, t);
        ldA(1, t); stA(1, t);
    }

    const int NPAN = D_MODEL / GBK;   // 32
#pragma unroll 1
    for (int p = 0; p < NPAN; p++) {
        if (p < NPAN - 1)
            asm volatile("cp.async.wait_group 1;" ::: "memory");
        else
            asm volatile("cp.async.wait_group 0;" ::: "memory");
        __syncthreads();

        float4 ar[4];
        const bool pre = (p + 2 < NPAN);
        if (pre) {
            ldA(p + 2, ar);
            stageB(p + 2);
        }

        const int s = p % NSTAGE;
        const uint32_t Ab32 = sb + (uint32_t)(s * (HST_A + HST_B)) * 2u;
        const uint32_t Bb32 = Ab32 + (uint32_t)HST_A * 2u;
#pragma unroll
        for (int ks = 0; ks < 2; ks++) {
            unsigned a[4][4], b[4][2];
#pragma unroll
            for (int mi = 0; mi < 4; mi++)
                LDSM4(a[mi][0], a[mi][1], a[mi][2], a[mi][3],
                      Ab32 + (a_base + mi * 16 * HSTR + ks * 16) * 2u);
#pragma unroll
            for (int q = 0; q < 2; q++)
                LDSM4(b[2 * q][0], b[2 * q][1], b[2 * q + 1][0], b[2 * q + 1][1],
                      Bb32 + (b_base + q * 16 * HSTR + ks * 16) * 2u);
#pragma unroll
            for (int mi = 0; mi < 4; mi++)
#pragma unroll
                for (int nj = 0; nj < 4; nj++)
                    mma_f16(acc[mi][nj], a[mi], b[nj]);
        }

        if (pre) stA(p + 2, ar);
    }

    // Epilogue
#pragma unroll
    for (int nj = 0; nj < 4; nj++) {
        const int col = bn + wn * 32 + nj * 8 + tg * 2;
        const float2 bv = *(const float2*)&bias[col];
#pragma unroll
        for (int mi = 0; mi < 4; mi++) {
            const int row0 = bm + wm * 64 + mi * 16 + g;
            float2 o0, o1;
            o0.x = acc[mi][nj][0] + bv.x;
            o0.y = acc[mi][nj][1] + bv.y;
            o1.x = acc[mi][nj][2] + bv.x;
            o1.y = acc[mi][nj][3] + bv.y;
            *(float2*)(C + (size_t)row0 * N + col)       = o0;
            *(float2*)(C + (size_t)(row0 + 8) * N + col) = o1;
        }
    }
}

// ---------------------------------------------------------------------------
// fp16 tensor-core sparse local-window attention.
// Block = (128 q, 1 head, 1 batch), 8 warps x 16 query rows.
// K/V/P in half, stride 72 halves (144B = 9x16B rows): ldmatrix conflict-free.
// S = Q@K^T: K rows as non-trans B-frag.  O += P@V: V rows as .trans B-frag.
// ---------------------------------------------------------------------------
#define HKS 72
#define HPS 72
#define KS_OFF 0
#define VS_OFF (256 * HKS * 2)                  // 36864
#define PS_OFF (2 * VS_OFF)                     // 73728
#define BS_OFF (PS_OFF + 8 * 16 * HPS * 2)      // 92160
#define ATTN_SMEM (BS_OFF + 132 * 4)            // 92688

__global__ __launch_bounds__(256, 2) void attn_h(
    const float* __restrict__ Q, const float* __restrict__ Kp,
    const float* __restrict__ Vp, const float* __restrict__ rel,
    float* __restrict__ O)
{
    extern __shared__ char smb[];
    __half* Ks = (__half*)(smb + KS_OFF);
    __half* Vs = (__half*)(smb + VS_OFF);
    float*  bsf = (float*)(smb + BS_OFF);
    const uint32_t sbase = smem_u32(smb);

    const int t0   = blockIdx.x * 128;
    const int h    = blockIdx.y;
    const int b    = blockIdx.z;
    const int base = t0 - WIN;
    const int tid  = threadIdx.x;
    const int warp = tid >> 5, lane = tid & 31;
    const int g = lane >> 2, tg = lane & 3;
    const int lj = lane >> 3, lr = lane & 7;

    const float* Kg = Kp + (size_t)b * T_SEQ * D_MODEL + h * DK;
    const float* Vg = Vp + (size_t)b * T_SEQ * D_MODEL + h * DK;

    // Stage 256-key K/V window as half
#pragma unroll
    for (int it = 0; it < 16; it++) {
        const int idx = tid + it * 256;
        const int key = idx >> 4, d4 = idx & 15;
        const int t   = base + key;
        float4 kv = make_float4(0.f, 0.f, 0.f, 0.f);
        float4 vv = make_float4(0.f, 0.f, 0.f, 0.f);
        if (t >= 0 && t < T_SEQ) {
            kv = *(const float4*)(Kg + (size_t)t * D_MODEL + d4 * 4);
            vv = *(const float4*)(Vg + (size_t)t * D_MODEL + d4 * 4);
        }
        *(__half2*)&Ks[key * HKS + d4 * 4]     = __floats2half2_rn(kv.x, kv.y);
        *(__half2*)&Ks[key * HKS + d4 * 4 + 2] = __floats2half2_rn(kv.z, kv.w);
        *(__half2*)&Vs[key * HKS + d4 * 4]     = __floats2half2_rn(vv.x, vv.y);
        *(__half2*)&Vs[key * HKS + d4 * 4 + 2] = __floats2half2_rn(vv.z, vv.w);
    }
    if (tid < 2 * WIN + 1)
        bsf[tid] = rel[(size_t)(tid + MAXD - WIN) * H_HEADS + h];

    // Q fragments (fp16), register-resident: qa[kt][0..3], kt = 4 k16-steps
    const int q0 = t0 + warp * 16;
    const float* Qg = Q + (size_t)(b * T_SEQ + q0) * D_MODEL + h * DK;
    unsigned qa[4][4];
#pragma unroll
    for (int kt = 0; kt < 4; kt++) {
        const int k0 = kt * 16 + 2 * tg;
        qa[kt][0] = h2u(__floats2half2_rn(Qg[(size_t)g       * D_MODEL + k0],
                                          Qg[(size_t)g       * D_MODEL + k0 + 1]));
        qa[kt][1] = h2u(__floats2half2_rn(Qg[(size_t)(g + 8) * D_MODEL + k0],
                                          Qg[(size_t)(g + 8) * D_MODEL + k0 + 1]));
        qa[kt][2] = h2u(__floats2half2_rn(Qg[(size_t)g       * D_MODEL + k0 + 8],
                                          Qg[(size_t)g       * D_MODEL + k0 + 9]));
        qa[kt][3] = h2u(__floats2half2_rn(Qg[(size_t)(g + 8) * D_MODEL + k0 + 8],
                                          Qg[(size_t)(g + 8) * D_MODEL + k0 + 9]));
    }
    __syncthreads();

    float oacc[8][4];
#pragma unroll
    for (int nt = 0; nt < 8; nt++)
#pragma unroll
        for (int r = 0; r < 4; r++) oacc[nt][r] = 0.f;
    float rs0 = 0.f, rs1 = 0.f;

    const uint32_t Pw32 = sbase + PS_OFF + (uint32_t)(warp * 16 * HPS) * 2u;
    __half* Pw = (__half*)(smb + PS_OFF) + warp * 16 * HPS;

#pragma unroll 1
    for (int c = 0; c < 4; c++) {
        // ---- S = Q @ K_chunk^T ----
        float sacc[8][4];
#pragma unroll
        for (int nt = 0; nt < 8; nt++)
#pragma unroll
            for (int r = 0; r < 4; r++) sacc[nt][r] = 0.f;
#pragma unroll
        for (int kt = 0; kt < 4; kt++) {
            unsigned kb[8][2];
#pragma unroll
            for (int q = 0; q < 4; q++) {
                const uint32_t row = (uint32_t)(c * 64 + (q * 2 + (lj >> 1)) * 8 + lr);
                LDSM4(kb[2 * q][0], kb[2 * q][1], kb[2 * q + 1][0], kb[2 * q + 1][1],
                      sbase + KS_OFF + (row * HKS + kt * 16 + (lj & 1) * 8) * 2u);
            }
#pragma unroll
            for (int nt = 0; nt < 8; nt++)
                mma_f16(sacc[nt], qa[kt], kb[nt]);
        }

        // ---- bias + band mask + exp; stage P (half) ----
        __syncwarp();
#pragma unroll
        for (int nt = 0; nt < 8; nt++) {
            const int col = c * 64 + nt * 8 + 2 * tg;
            const int tk  = base + col;
            const int d0  = tk - (q0 + g);
            const int d2  = tk - (q0 + 8 + g);
            float e0 = 0.f, e1 = 0.f, e2 = 0.f, e3 = 0.f;
            if (tk >= 0 && tk < T_SEQ) {
                if (d0 >= -WIN && d0 <= WIN) e0 = __expf(sacc[nt][0] * 0.125f + bsf[d0 + WIN]);
                if (d2 >= -WIN && d2 <= WIN) e2 = __expf(sacc[nt][2] * 0.125f + bsf[d2 + WIN]);
            }
            if (tk + 1 >= 0 && tk + 1 < T_SEQ) {
                if (d0 + 1 >= -WIN && d0 + 1 <= WIN) e1 = __expf(sacc[nt][1] * 0.125f + bsf[d0 + 1 + WIN]);
                if (d2 + 1 >= -WIN && d2 + 1 <= WIN) e3 = __expf(sacc[nt][3] * 0.125f + bsf[d2 + 1 + WIN]);
            }
            rs0 += e0 + e1;
            rs1 += e2 + e3;
            *(__half2*)&Pw[(size_t)g       * HPS + nt * 8 + 2 * tg] = __floats2half2_rn(e0, e1);
            *(__half2*)&Pw[(size_t)(g + 8) * HPS + nt * 8 + 2 * tg] = __floats2half2_rn(e2, e3);
        }
        __syncwarp();

        // ---- O += P_chunk @ V_chunk ----
#pragma unroll
        for (int kt = 0; kt < 4; kt++) {
            unsigned pa[4];
            LDSM4(pa[0], pa[1], pa[2], pa[3],
                  Pw32 + ((uint32_t)(((lj & 1) * 8 + lr) * HPS) + kt * 16 + (lj >> 1) * 8) * 2u);
            unsigned vb[8][2];
#pragma unroll
            for (int q = 0; q < 4; q++) {
                const uint32_t row = (uint32_t)(c * 64 + kt * 16 + (lj & 1) * 8 + lr);
                LDSM4T(vb[2 * q][0], vb[2 * q][1], vb[2 * q + 1][0], vb[2 * q + 1][1],
                       sbase + VS_OFF + (row * HKS + (q * 2 + (lj >> 1)) * 8) * 2u);
            }
#pragma unroll
            for (int nt = 0; nt < 8; nt++)
                mma_f16(oacc[nt], pa, vb[nt]);
        }
    }

    // ---- row sums (quad reduce) + normalize + store ----
    rs0 += __shfl_xor_sync(0xffffffffu, rs0, 1);
    rs0 += __shfl_xor_sync(0xffffffffu, rs0, 2);
    rs1 += __shfl_xor_sync(0xffffffffu, rs1, 1);
    rs1 += __shfl_xor_sync(0xffffffffu, rs1, 2);
    const float i0 = 1.f / rs0, i1 = 1.f / rs1;

    float* Og = O + (size_t)(b * T_SEQ + q0) * D_MODEL + h * DK;
#pragma unroll
    for (int nt = 0; nt < 8; nt++) {
        *(float2*)&Og[(size_t)g       * D_MODEL + nt * 8 + 2 * tg] =
            make_float2(oacc[nt][0] * i0, oacc[nt][1] * i0);
        *(float2*)&Og[(size_t)(g + 8) * D_MODEL + nt * 8 + 2 * tg] =
            make_float2(oacc[nt][2] * i1, oacc[nt][3] * i1);
    }
}

// ---------------------------------------------------------------------------
// Launch
// ---------------------------------------------------------------------------
extern "C" void kernel_launch(void* const* d_in, const int* in_sizes, int n_in,
                              void* d_out, int out_size)
{
    const float* q_in = (const float*)d_in[0];
    const float* k_in = (const float*)d_in[1];
    const float* v_in = (const float*)d_in[2];
    const float* Wq   = (const float*)d_in[3];
    const float* bq   = (const float*)d_in[4];
    const float* Wk   = (const float*)d_in[5];
    const float* bk   = (const float*)d_in[6];
    const float* Wv   = (const float*)d_in[7];
    const float* bv   = (const float*)d_in[8];
    const float* Wo   = (const float*)d_in[9];
    const float* bo   = (const float*)d_in[10];
    const float* rel  = (const float*)d_in[11];
    float* out = (float*)d_out;

    float *pQ, *pK, *pV, *pA;
    __half* pWT;
    cudaGetSymbolAddress((void**)&pQ, g_Q);
    cudaGetSymbolAddress((void**)&pK, g_K);
    cudaGetSymbolAddress((void**)&pV, g_V);
    cudaGetSymbolAddress((void**)&pA, g_A);
    cudaGetSymbolAddress((void**)&pWT, g_WT);

    cudaFuncSetAttribute(hgemm_pipe, cudaFuncAttributeMaxDynamicSharedMemorySize,
                         (int)GEMM_SMEM);
    cudaFuncSetAttribute(attn_h, cudaFuncAttributeMaxDynamicSharedMemorySize,
                         (int)ATTN_SMEM);

    const size_t WSZ = (size_t)D_MODEL * D_MODEL;

    wtrans_h<<<dim3(32, 32, 4), dim3(32, 8)>>>(Wq, Wk, Wv, Wo, pWT);

    dim3 g3(D_MODEL / GBN, M_ROWS / GBM, 3);
    hgemm_pipe<<<g3, 256, GEMM_SMEM>>>(q_in, k_in, v_in, pWT,
                                       bq, bk, bv, pQ, pK, pV);

    attn_h<<<dim3(T_SEQ / 128, H_HEADS, B_SZ), 256, ATTN_SMEM>>>(pQ, pK, pV, rel, pA);

    dim3 g1(D_MODEL / GBN, M_ROWS / GBM, 1);
    hgemm_pipe<<<g1, 256, GEMM_SMEM>>>(pA, pA, pA, pWT + 3 * WSZ,
                                       bo, bo, bo, out, out, out);
}

// round 11
// speedup vs baseline: 5.5487x; 1.1458x over previous
#include <cuda_runtime.h>
#include <cuda_fp16.h>
#include <cstdint>

// Problem constants
#define B_SZ    2
#define T_SEQ   2048
#define D_MODEL 1024
#define H_HEADS 16
#define DK      64
#define M_ROWS  (B_SZ * T_SEQ)   // 4096
#define WIN     64
#define MAXD    128

// ---------------------------------------------------------------------------
// Scratch (all fp16 intermediates)
// ---------------------------------------------------------------------------
__device__ __half g_Qh[(size_t)M_ROWS * D_MODEL];
__device__ __half g_Kh[(size_t)M_ROWS * D_MODEL];
__device__ __half g_Vh[(size_t)M_ROWS * D_MODEL];
__device__ __half g_Ah[(size_t)M_ROWS * D_MODEL];
__device__ __half g_WH[(size_t)4 * D_MODEL * D_MODEL];   // half(W[k][n]), same layout

__device__ __forceinline__ void mma_f16(float* c, const unsigned* a, const unsigned* b) {
    asm volatile(
        "mma.sync.aligned.m16n8k16.row.col.f32.f16.f16.f32 "
        "{%0,%1,%2,%3}, {%4,%5,%6,%7}, {%8,%9}, {%0,%1,%2,%3};\n"
        : "+f"(c[0]), "+f"(c[1]), "+f"(c[2]), "+f"(c[3])
        : "r"(a[0]), "r"(a[1]), "r"(a[2]), "r"(a[3]), "r"(b[0]), "r"(b[1]));
}

#define LDSM4(R0, R1, R2, R3, ADDR)                                           \
    asm volatile("ldmatrix.sync.aligned.m8n8.x4.shared.b16 {%0,%1,%2,%3}, [%4];" \
                 : "=r"(R0), "=r"(R1), "=r"(R2), "=r"(R3) : "r"(ADDR))
#define LDSM4T(R0, R1, R2, R3, ADDR)                                          \
    asm volatile("ldmatrix.sync.aligned.m8n8.x4.trans.shared.b16 {%0,%1,%2,%3}, [%4];" \
                 : "=r"(R0), "=r"(R1), "=r"(R2), "=r"(R3) : "r"(ADDR))

__device__ __forceinline__ uint32_t smem_u32(const void* p) {
    uint32_t a;
    asm("{ .reg .u64 t; cvta.to.shared.u64 t, %1; cvt.u32.u64 %0, t; }" : "=r"(a) : "l"(p));
    return a;
}

__device__ __forceinline__ void cp16(uint32_t dst, const void* src) {
    asm volatile("cp.async.cg.shared.global [%0], [%1], 16;" :: "r"(dst), "l"(src));
}
// Zero-fill variant: copies 16B if v, else fills 16B with zeros.
__device__ __forceinline__ void cp16z(uint32_t dst, const void* src, bool v) {
    int sz = v ? 16 : 0;
    asm volatile("cp.async.cg.shared.global [%0], [%1], 16, %2;"
                 :: "r"(dst), "l"(src), "r"(sz));
}

// ---------------------------------------------------------------------------
// Weight elementwise fp16 convert (NO transpose): WH[z][k][n] = half(W[k][n]).
// grid (1024, 4), 256 threads, one float4 -> 4 halves per thread.
// ---------------------------------------------------------------------------
__global__ __launch_bounds__(256) void welem_h(
    const float* __restrict__ w0, const float* __restrict__ w1,
    const float* __restrict__ w2, const float* __restrict__ w3,
    __half* __restrict__ dst)
{
    const int z = blockIdx.y;
    const float* src = (z == 0) ? w0 : (z == 1) ? w1 : (z == 2) ? w2 : w3;
    __half* d = dst + (size_t)z * D_MODEL * D_MODEL;
    const size_t i4 = (size_t)blockIdx.x * 256 + threadIdx.x;
    float4 v = ((const float4*)src)[i4];
    __half2 h0 = __floats2half2_rn(v.x, v.y);
    __half2 h1 = __floats2half2_rn(v.z, v.w);
    *(__half2*)(d + i4 * 4)     = h0;
    *(__half2*)(d + i4 * 4 + 2) = h1;
}

// ---------------------------------------------------------------------------
// fp16 mma.sync GEMM. Tile 128x128, BK=32, 8 warps (2m x 4n), m16n8k16.
// A SMEM: [m][k] stride 40 halves (80B).  B SMEM: [k][n] stride 136 halves
// (272B = 17x16B) -> B fragments via ldmatrix.trans (no weight transpose).
// AMODE: 0 = A fp32 (LDG+cvt+STS, register prefetch), 1 = A fp16 (cp.async).
// CMODE: 0 = C fp32, 1 = C fp16.
// ---------------------------------------------------------------------------
#define GBM 128
#define GBN 128
#define GBK 32
#define HSTR 40
#define BHSTR 136
#define HST_A (GBM * HSTR)      // 5120 halves
#define HST_B (GBK * BHSTR)     // 4352 halves
#define NSTAGE 3
#define GEMM_SMEM (NSTAGE * (HST_A + HST_B) * 2)   // 56832 B

template<int AMODE, int CMODE>
__global__ __launch_bounds__(256, 2) void hgemm_t(
    const void* __restrict__ A0, const void* __restrict__ A1, const void* __restrict__ A2,
    const __half* __restrict__ Wh,
    const float* __restrict__ b0, const float* __restrict__ b1, const float* __restrict__ b2,
    void* __restrict__ C0, void* __restrict__ C1, void* __restrict__ C2)
{
    extern __shared__ __half shh[];
    const uint32_t sb = smem_u32(shh);

    const int z = blockIdx.z;
    const void* Av    = (z == 0) ? A0 : (z == 1) ? A1 : A2;
    const __half* W   = Wh + (size_t)z * D_MODEL * D_MODEL;
    const float* bias = (z == 0) ? b0 : (z == 1) ? b1 : b2;
    void* Cv          = (z == 0) ? C0 : (z == 1) ? C1 : C2;

    const int N = D_MODEL;
    const int tid  = threadIdx.x;
    const int bm   = blockIdx.y * GBM;
    const int bn   = blockIdx.x * GBN;
    const int warp = tid >> 5, lane = tid & 31;
    const int wm = warp & 1;
    const int wn = warp >> 1;
    const int g  = lane >> 2;
    const int tg = lane & 3;
    const int lj = lane >> 3, lr = lane & 7;

    const int am0 = tid >> 3, akq = tid & 7;   // AMODE==0 loader
    const uint32_t a_base = (uint32_t)((wm * 64 + (lj & 1) * 8 + lr) * HSTR + (lj >> 1) * 8);

    float acc[4][4][4];
#pragma unroll
    for (int mi = 0; mi < 4; mi++)
#pragma unroll
        for (int nj = 0; nj < 4; nj++)
#pragma unroll
            for (int r = 0; r < 4; r++) acc[mi][nj][r] = 0.f;

    auto stageB = [&](int p) {
        const int s = p % NSTAGE;
        const uint32_t Bsb = sb + (uint32_t)(s * (HST_A + HST_B) + HST_A) * 2u;
        const int kp = p * GBK;
        // 32 k-rows x 16 n-chunks = 512 chunks of 16B, 2 per thread
#pragma unroll
        for (int i = 0; i < 2; i++) {
            const int idx = tid + i * 256;
            const int row = idx >> 4, c = idx & 15;
            cp16(Bsb + (uint32_t)(row * (BHSTR * 2) + c * 16),
                 W + (size_t)(kp + row) * N + bn + c * 8);
        }
    };
    auto stageA_h = [&](int p) {
        const int s = p % NSTAGE;
        const uint32_t Asb = sb + (uint32_t)(s * (HST_A + HST_B)) * 2u;
        const int kp = p * GBK;
        const __half* Ah = (const __half*)Av;
#pragma unroll
        for (int i = 0; i < 2; i++) {   // 128 rows x 4 chunks = 512, 2 per thread
            const int idx = tid + i * 256;
            const int row = idx >> 2, c = idx & 3;
            cp16(Asb + (uint32_t)(row * (HSTR * 2) + c * 16),
                 Ah + (size_t)(bm + row) * D_MODEL + kp + c * 8);
        }
    };
    auto ldA_f = [&](int p, float4* ar) {
        const int kp = p * GBK;
        const float* Af = (const float*)Av;
#pragma unroll
        for (int i = 0; i < 4; i++)
            ar[i] = *(const float4*)(Af + (size_t)(bm + am0 + 32 * i) * D_MODEL + kp + akq * 4);
    };
    auto stA_f = [&](int p, const float4* ar) {
        const int s = p % NSTAGE;
        __half* As = shh + s * (HST_A + HST_B);
#pragma unroll
        for (int i = 0; i < 4; i++) {
            __half2 h0 = __floats2half2_rn(ar[i].x, ar[i].y);
            __half2 h1 = __floats2half2_rn(ar[i].z, ar[i].w);
            *(__half2*)&As[(am0 + 32 * i) * HSTR + akq * 4]     = h0;
            *(__half2*)&As[(am0 + 32 * i) * HSTR + akq * 4 + 2] = h1;
        }
    };
    auto stage = [&](int p) {
        if (AMODE == 1) stageA_h(p);
        stageB(p);
        asm volatile("cp.async.commit_group;" ::: "memory");
    };

    stage(0);
    stage(1);
    if (AMODE == 0) {
        float4 t[4];
        ldA_f(0, t); stA_f(0, t);
        ldA_f(1, t); stA_f(1, t);
    }

    const int NPAN = D_MODEL / GBK;   // 32
#pragma unroll 1
    for (int p = 0; p < NPAN; p++) {
        if (p < NPAN - 1)
            asm volatile("cp.async.wait_group 1;" ::: "memory");
        else
            asm volatile("cp.async.wait_group 0;" ::: "memory");
        __syncthreads();

        float4 ar[4];
        const bool pre = (p + 2 < NPAN);
        if (pre) {
            if (AMODE == 0) ldA_f(p + 2, ar);
            stage(p + 2);
        }

        const int s = p % NSTAGE;
        const uint32_t Ab32 = sb + (uint32_t)(s * (HST_A + HST_B)) * 2u;
        const uint32_t Bb32 = Ab32 + (uint32_t)HST_A * 2u;
#pragma unroll
        for (int ks = 0; ks < 2; ks++) {
            unsigned a[4][4], b[4][2];
#pragma unroll
            for (int mi = 0; mi < 4; mi++)
                LDSM4(a[mi][0], a[mi][1], a[mi][2], a[mi][3],
                      Ab32 + (a_base + mi * 16 * HSTR + ks * 16) * 2u);
#pragma unroll
            for (int q = 0; q < 2; q++)
                LDSM4T(b[2 * q][0], b[2 * q][1], b[2 * q + 1][0], b[2 * q + 1][1],
                       Bb32 + ((uint32_t)((ks * 16 + (lj & 1) * 8 + lr) * BHSTR)
                               + wn * 32 + (q * 2 + (lj >> 1)) * 8) * 2u);
#pragma unroll
            for (int mi = 0; mi < 4; mi++)
#pragma unroll
                for (int nj = 0; nj < 4; nj++)
                    mma_f16(acc[mi][nj], a[mi], b[nj]);
        }

        if (pre && AMODE == 0) stA_f(p + 2, ar);
    }

    // Epilogue: bias + store
#pragma unroll
    for (int nj = 0; nj < 4; nj++) {
        const int col = bn + wn * 32 + nj * 8 + tg * 2;
        const float2 bv = *(const float2*)&bias[col];
#pragma unroll
        for (int mi = 0; mi < 4; mi++) {
            const int row0 = bm + wm * 64 + mi * 16 + g;
            if (CMODE == 0) {
                float* C = (float*)Cv;
                float2 o0, o1;
                o0.x = acc[mi][nj][0] + bv.x;
                o0.y = acc[mi][nj][1] + bv.y;
                o1.x = acc[mi][nj][2] + bv.x;
                o1.y = acc[mi][nj][3] + bv.y;
                *(float2*)(C + (size_t)row0 * N + col)       = o0;
                *(float2*)(C + (size_t)(row0 + 8) * N + col) = o1;
            } else {
                __half* C = (__half*)Cv;
                *(__half2*)(C + (size_t)row0 * N + col) =
                    __floats2half2_rn(acc[mi][nj][0] + bv.x, acc[mi][nj][1] + bv.y);
                *(__half2*)(C + (size_t)(row0 + 8) * N + col) =
                    __floats2half2_rn(acc[mi][nj][2] + bv.x, acc[mi][nj][3] + bv.y);
            }
        }
    }
}

// ---------------------------------------------------------------------------
// fp16 attention, cp.async staging, half in / half out.
// ---------------------------------------------------------------------------
#define HKS 72
#define HPS 72
#define KS_OFF 0
#define VS_OFF (256 * HKS * 2)                  // 36864
#define PS_OFF (2 * VS_OFF)                     // 73728
#define BS_OFF (PS_OFF + 8 * 16 * HPS * 2)      // 92160
#define ATTN_SMEM (BS_OFF + 132 * 4)            // 92688

__global__ __launch_bounds__(256, 2) void attn_h(
    const __half* __restrict__ Q, const __half* __restrict__ Kp,
    const __half* __restrict__ Vp, const float* __restrict__ rel,
    __half* __restrict__ O)
{
    extern __shared__ char smb[];
    float*  bsf = (float*)(smb + BS_OFF);
    const uint32_t sbase = smem_u32(smb);

    const int t0   = blockIdx.x * 128;
    const int h    = blockIdx.y;
    const int b    = blockIdx.z;
    const int base = t0 - WIN;
    const int tid  = threadIdx.x;
    const int warp = tid >> 5, lane = tid & 31;
    const int g = lane >> 2, tg = lane & 3;
    const int lj = lane >> 3, lr = lane & 7;

    const __half* Kg = Kp + (size_t)b * T_SEQ * D_MODEL + h * DK;
    const __half* Vg = Vp + (size_t)b * T_SEQ * D_MODEL + h * DK;

    // Stage 256-key K/V window via cp.async (16 chunks per thread)
#pragma unroll
    for (int it = 0; it < 16; it++) {
        const int idx = tid + it * 256;          // 0..4095
        const int sel = idx >> 11;               // 0 = K, 1 = V
        const int r   = idx & 2047;
        const int key = r >> 3, d4 = r & 7;
        const int t   = base + key;
        const uint32_t dst = sbase + (sel ? VS_OFF : KS_OFF)
                           + (uint32_t)(key * HKS + d4 * 8) * 2u;
        const __half* src = (sel ? Vg : Kg) + (size_t)t * D_MODEL + d4 * 8;
        cp16z(dst, src, t >= 0 && t < T_SEQ);
    }
    asm volatile("cp.async.commit_group;" ::: "memory");
    if (tid < 2 * WIN + 1)
        bsf[tid] = rel[(size_t)(tid + MAXD - WIN) * H_HEADS + h];

    // Q fragments (half, register-resident)
    const int q0 = t0 + warp * 16;
    const __half* Qg = Q + (size_t)(b * T_SEQ + q0) * D_MODEL + h * DK;
    unsigned qa[4][4];
#pragma unroll
    for (int kt = 0; kt < 4; kt++) {
        const int k0 = kt * 16 + 2 * tg;
        qa[kt][0] = *(const unsigned*)(Qg + (size_t)g       * D_MODEL + k0);
        qa[kt][1] = *(const unsigned*)(Qg + (size_t)(g + 8) * D_MODEL + k0);
        qa[kt][2] = *(const unsigned*)(Qg + (size_t)g       * D_MODEL + k0 + 8);
        qa[kt][3] = *(const unsigned*)(Qg + (size_t)(g + 8) * D_MODEL + k0 + 8);
    }
    asm volatile("cp.async.wait_group 0;" ::: "memory");
    __syncthreads();

    float oacc[8][4];
#pragma unroll
    for (int nt = 0; nt < 8; nt++)
#pragma unroll
        for (int r = 0; r < 4; r++) oacc[nt][r] = 0.f;
    float rs0 = 0.f, rs1 = 0.f;

    const uint32_t Pw32 = sbase + PS_OFF + (uint32_t)(warp * 16 * HPS) * 2u;
    __half* Pw = (__half*)(smb + PS_OFF) + warp * 16 * HPS;

#pragma unroll 1
    for (int c = 0; c < 4; c++) {
        // ---- S = Q @ K_chunk^T ----
        float sacc[8][4];
#pragma unroll
        for (int nt = 0; nt < 8; nt++)
#pragma unroll
            for (int r = 0; r < 4; r++) sacc[nt][r] = 0.f;
#pragma unroll
        for (int kt = 0; kt < 4; kt++) {
            unsigned kb[8][2];
#pragma unroll
            for (int q = 0; q < 4; q++) {
                const uint32_t row = (uint32_t)(c * 64 + (q * 2 + (lj >> 1)) * 8 + lr);
                LDSM4(kb[2 * q][0], kb[2 * q][1], kb[2 * q + 1][0], kb[2 * q + 1][1],
                      sbase + KS_OFF + (row * HKS + kt * 16 + (lj & 1) * 8) * 2u);
            }
#pragma unroll
            for (int nt = 0; nt < 8; nt++)
                mma_f16(sacc[nt], qa[kt], kb[nt]);
        }

        // ---- bias + band mask + exp; stage P (half) ----
        __syncwarp();
#pragma unroll
        for (int nt = 0; nt < 8; nt++) {
            const int col = c * 64 + nt * 8 + 2 * tg;
            const int tk  = base + col;
            const int d0  = tk - (q0 + g);
            const int d2  = tk - (q0 + 8 + g);
            float e0 = 0.f, e1 = 0.f, e2 = 0.f, e3 = 0.f;
            if (tk >= 0 && tk < T_SEQ) {
                if (d0 >= -WIN && d0 <= WIN) e0 = __expf(sacc[nt][0] * 0.125f + bsf[d0 + WIN]);
                if (d2 >= -WIN && d2 <= WIN) e2 = __expf(sacc[nt][2] * 0.125f + bsf[d2 + WIN]);
            }
            if (tk + 1 >= 0 && tk + 1 < T_SEQ) {
                if (d0 + 1 >= -WIN && d0 + 1 <= WIN) e1 = __expf(sacc[nt][1] * 0.125f + bsf[d0 + 1 + WIN]);
                if (d2 + 1 >= -WIN && d2 + 1 <= WIN) e3 = __expf(sacc[nt][3] * 0.125f + bsf[d2 + 1 + WIN]);
            }
            rs0 += e0 + e1;
            rs1 += e2 + e3;
            *(__half2*)&Pw[(size_t)g       * HPS + nt * 8 + 2 * tg] = __floats2half2_rn(e0, e1);
            *(__half2*)&Pw[(size_t)(g + 8) * HPS + nt * 8 + 2 * tg] = __floats2half2_rn(e2, e3);
        }
        __syncwarp();

        // ---- O += P_chunk @ V_chunk ----
#pragma unroll
        for (int kt = 0; kt < 4; kt++) {
            unsigned pa[4];
            LDSM4(pa[0], pa[1], pa[2], pa[3],
                  Pw32 + ((uint32_t)(((lj & 1) * 8 + lr) * HPS) + kt * 16 + (lj >> 1) * 8) * 2u);
            unsigned vb[8][2];
#pragma unroll
            for (int q = 0; q < 4; q++) {
                const uint32_t row = (uint32_t)(c * 64 + kt * 16 + (lj & 1) * 8 + lr);
                LDSM4T(vb[2 * q][0], vb[2 * q][1], vb[2 * q + 1][0], vb[2 * q + 1][1],
                       sbase + VS_OFF + (row * HKS + (q * 2 + (lj >> 1)) * 8) * 2u);
            }
#pragma unroll
            for (int nt = 0; nt < 8; nt++)
                mma_f16(oacc[nt], pa, vb[nt]);
        }
    }

    // ---- row sums + normalize + store (half) ----
    rs0 += __shfl_xor_sync(0xffffffffu, rs0, 1);
    rs0 += __shfl_xor_sync(0xffffffffu, rs0, 2);
    rs1 += __shfl_xor_sync(0xffffffffu, rs1, 1);
    rs1 += __shfl_xor_sync(0xffffffffu, rs1, 2);
    const float i0 = 1.f / rs0, i1 = 1.f / rs1;

    __half* Og = O + (size_t)(b * T_SEQ + q0) * D_MODEL + h * DK;
#pragma unroll
    for (int nt = 0; nt < 8; nt++) {
        *(__half2*)(Og + (size_t)g       * D_MODEL + nt * 8 + 2 * tg) =
            __floats2half2_rn(oacc[nt][0] * i0, oacc[nt][1] * i0);
        *(__half2*)(Og + (size_t)(g + 8) * D_MODEL + nt * 8 + 2 * tg) =
            __floats2half2_rn(oacc[nt][2] * i1, oacc[nt][3] * i1);
    }
}

// ---------------------------------------------------------------------------
// Launch
// ---------------------------------------------------------------------------
extern "C" void kernel_launch(void* const* d_in, const int* in_sizes, int n_in,
                              void* d_out, int out_size)
{
    const float* q_in = (const float*)d_in[0];
    const float* k_in = (const float*)d_in[1];
    const float* v_in = (const float*)d_in[2];
    const float* Wq   = (const float*)d_in[3];
    const float* bq   = (const float*)d_in[4];
    const float* Wk   = (const float*)d_in[5];
    const float* bk   = (const float*)d_in[6];
    const float* Wv   = (const float*)d_in[7];
    const float* bv   = (const float*)d_in[8];
    const float* Wo   = (const float*)d_in[9];
    const float* bo   = (const float*)d_in[10];
    const float* rel  = (const float*)d_in[11];
    float* out = (float*)d_out;

    __half *pQ, *pK, *pV, *pA, *pWH;
    cudaGetSymbolAddress((void**)&pQ, g_Qh);
    cudaGetSymbolAddress((void**)&pK, g_Kh);
    cudaGetSymbolAddress((void**)&pV, g_Vh);
    cudaGetSymbolAddress((void**)&pA, g_Ah);
    cudaGetSymbolAddress((void**)&pWH, g_WH);

    cudaFuncSetAttribute(hgemm_t<0, 1>, cudaFuncAttributeMaxDynamicSharedMemorySize,
                         (int)GEMM_SMEM);
    cudaFuncSetAttribute(hgemm_t<1, 0>, cudaFuncAttributeMaxDynamicSharedMemorySize,
                         (int)GEMM_SMEM);
    cudaFuncSetAttribute(attn_h, cudaFuncAttributeMaxDynamicSharedMemorySize,
                         (int)ATTN_SMEM);

    const size_t WSZ = (size_t)D_MODEL * D_MODEL;

    // Elementwise fp16 weight conversion (no transpose).
    welem_h<<<dim3(D_MODEL * D_MODEL / 4 / 256, 4), 256>>>(Wq, Wk, Wv, Wo, pWH);

    // Fused Q/K/V projections: f32 in, half out.
    dim3 g3(D_MODEL / GBN, M_ROWS / GBM, 3);
    hgemm_t<0, 1><<<g3, 256, GEMM_SMEM>>>(q_in, k_in, v_in, pWH,
                                          bq, bk, bv, pQ, pK, pV);

    attn_h<<<dim3(T_SEQ / 128, H_HEADS, B_SZ), 256, ATTN_SMEM>>>(pQ, pK, pV, rel, pA);

    // Output projection: half in, f32 out.
    dim3 g1(D_MODEL / GBN, M_ROWS / GBM, 1);
    hgemm_t<1, 0><<<g1, 256, GEMM_SMEM>>>(pA, pA, pA, pWH + 3 * WSZ,
                                          bo, bo, bo, out, out, out);
}